// round 3
// baseline (speedup 1.0000x reference)
#include <cuda_runtime.h>
#include <math.h>

// Problem constants
#define BB 2
#define SQ 2048
#define DD 512
#define NH 8
#define HD 64

static __device__ __forceinline__ float neg_big() { return -1e30f; }

#define SCALE 0.125f   // 1/sqrt(64)
#define CBIAS 0.5f

// Scratch (device globals; no allocation allowed)
__device__ float g_Q[BB * SQ * DD];
__device__ float g_K[BB * SQ * DD];
__device__ float g_V[BB * SQ * DD];
__device__ float g_ctx[BB * SQ * DD];
__device__ float g_bias[(size_t)BB * SQ * SQ];

// ---------------------------------------------------------------------------
// Generic tiled GEMM: C[M,N] = A[M,K] @ W[N,K]^T + bias[N]
// 64x64 tile, BK=32, 16x16 threads, 4x4 per thread.
// ---------------------------------------------------------------------------
__device__ __forceinline__ void gemm_nt_64x64(
    const float* __restrict__ A, const float* __restrict__ W,
    const float* __restrict__ bias, float* __restrict__ C,
    int N, int K, int m0, int n0)
{
    __shared__ float As[32][65];
    __shared__ float Ws[32][65];

    const int tx = threadIdx.x;          // 0..15
    const int ty = threadIdx.y;          // 0..15
    const int tid = ty * 16 + tx;

    float acc[4][4] = {};

    for (int k0 = 0; k0 < K; k0 += 32) {
        #pragma unroll
        for (int i = 0; i < 8; i++) {
            int e = tid + i * 256;       // 0..2047
            int r = e >> 5;              // 0..63
            int c = e & 31;              // 0..31
            As[c][r] = A[(size_t)(m0 + r) * K + k0 + c];
            Ws[c][r] = W[(size_t)(n0 + r) * K + k0 + c];
        }
        __syncthreads();

        #pragma unroll 8
        for (int kk = 0; kk < 32; kk++) {
            float a[4], b[4];
            #pragma unroll
            for (int i = 0; i < 4; i++) a[i] = As[kk][ty * 4 + i];
            #pragma unroll
            for (int j = 0; j < 4; j++) b[j] = Ws[kk][tx * 4 + j];
            #pragma unroll
            for (int i = 0; i < 4; i++)
                #pragma unroll
                for (int j = 0; j < 4; j++)
                    acc[i][j] = fmaf(a[i], b[j], acc[i][j]);
        }
        __syncthreads();
    }

    #pragma unroll
    for (int i = 0; i < 4; i++) {
        #pragma unroll
        for (int j = 0; j < 4; j++) {
            int n = n0 + tx * 4 + j;
            C[(size_t)(m0 + ty * 4 + i) * N + n] = acc[i][j] + bias[n];
        }
    }
}

// ---------------------------------------------------------------------------
// QKV projections: z selects which projection
// ---------------------------------------------------------------------------
__global__ void qkv_kernel(
    const float* __restrict__ x,
    const float* __restrict__ Wq, const float* __restrict__ bq,
    const float* __restrict__ Wk, const float* __restrict__ bk,
    const float* __restrict__ Wv, const float* __restrict__ bv)
{
    const float* W; const float* bias; float* out;
    if (blockIdx.z == 0)      { W = Wq; bias = bq; out = g_Q; }
    else if (blockIdx.z == 1) { W = Wk; bias = bk; out = g_K; }
    else                      { W = Wv; bias = bv; out = g_V; }
    gemm_nt_64x64(x, W, bias, out, DD, DD, blockIdx.y * 64, blockIdx.x * 64);
}

// ---------------------------------------------------------------------------
// Combined additive bias: ipa + assoc + attn_mask + concept + padding
// NOTE: concept_ids is int32 on device (JAX x64-disabled downcasts int64).
// ---------------------------------------------------------------------------
__global__ void bias_kernel(
    const float* __restrict__ ipa, const float* __restrict__ assoc,
    const float* __restrict__ amask,
    const int* __restrict__ cid, const unsigned char* __restrict__ kpm)
{
    int idx = blockIdx.x * 256 + threadIdx.x;   // < BB*SQ*SQ = 8388608 (fits int)
    int k = idx & (SQ - 1);
    int t = idx >> 11;        // SQ = 2048 = 2^11
    int q = t & (SQ - 1);
    int b = t >> 11;

    int cq = cid[b * SQ + q];
    int ck = cid[b * SQ + k];
    float v = ipa[idx] + assoc[idx] + amask[q * SQ + k];
    if (cq == ck && cq >= 0 && ck >= 0 && q != k) v += CBIAS;
    if (kpm[b * SQ + k]) v = neg_big();
    g_bias[idx] = v;
}

// ---------------------------------------------------------------------------
// Fused flash-style attention: per (b, h, 64-query tile).
// Online softmax over 64-wide key tiles. fp32 SIMT.
// ---------------------------------------------------------------------------
__global__ void attn_kernel()
{
    extern __shared__ float sm[];
    float (*Qt)[65] = (float(*)[65])(sm);                 // [d][q]
    float (*Kt)[65] = (float(*)[65])(sm + 64 * 65);       // [d][k]
    float (*Vs)[65] = (float(*)[65])(sm + 2 * 64 * 65);   // [k][d]
    float (*Ps)[65] = (float(*)[65])(sm + 3 * 64 * 65);   // [q][k] scores then probs
    float* row_m = sm + 4 * 64 * 65;
    float* row_l = row_m + 64;
    float* row_c = row_l + 64;

    const int tx = threadIdx.x, ty = threadIdx.y;
    const int tid = ty * 16 + tx;
    const int q0 = blockIdx.x * 64;
    const int h  = blockIdx.y;
    const int b  = blockIdx.z;

    const float* Qg = g_Q + ((size_t)b * SQ + q0) * DD + h * HD;
    #pragma unroll
    for (int e = tid; e < 4096; e += 256) {
        int q = e >> 6, d = e & 63;
        Qt[d][q] = Qg[q * DD + d] * SCALE;
    }
    if (tid < 64) { row_m[tid] = neg_big(); row_l[tid] = 0.0f; }

    float acc[4][4] = {};
    __syncthreads();

    for (int kt = 0; kt < SQ / 64; kt++) {
        const int k0 = kt * 64;
        const float* Kg = g_K + ((size_t)b * SQ + k0) * DD + h * HD;
        const float* Vg = g_V + ((size_t)b * SQ + k0) * DD + h * HD;
        #pragma unroll
        for (int e = tid; e < 4096; e += 256) {
            int k = e >> 6, d = e & 63;
            Kt[d][k] = Kg[k * DD + d];
            Vs[k][d] = Vg[k * DD + d];
        }
        __syncthreads();

        // S = Q @ K^T (4x4 register tile)
        float s[4][4] = {};
        #pragma unroll 8
        for (int d = 0; d < 64; d++) {
            float a[4], bb[4];
            #pragma unroll
            for (int i = 0; i < 4; i++) a[i] = Qt[d][ty * 4 + i];
            #pragma unroll
            for (int j = 0; j < 4; j++) bb[j] = Kt[d][tx * 4 + j];
            #pragma unroll
            for (int i = 0; i < 4; i++)
                #pragma unroll
                for (int j = 0; j < 4; j++)
                    s[i][j] = fmaf(a[i], bb[j], s[i][j]);
        }

        // Add combined bias, stage scores into smem
        const float* Bg = g_bias + ((size_t)b * SQ + q0) * SQ + k0;
        #pragma unroll
        for (int i = 0; i < 4; i++)
            #pragma unroll
            for (int j = 0; j < 4; j++)
                Ps[ty * 4 + i][tx * 4 + j] = s[i][j] + Bg[(size_t)(ty * 4 + i) * SQ + tx * 4 + j];
        __syncthreads();

        // Online softmax per row (64 rows, one thread each)
        if (tid < 64) {
            const int r = tid;
            float mo = row_m[r];
            float mx = mo;
            #pragma unroll 16
            for (int c = 0; c < 64; c++) mx = fmaxf(mx, Ps[r][c]);
            float corr = __expf(mo - mx);
            float sum = 0.0f;
            #pragma unroll 16
            for (int c = 0; c < 64; c++) {
                float p = __expf(Ps[r][c] - mx);
                Ps[r][c] = p;
                sum += p;
            }
            row_l[r] = row_l[r] * corr + sum;
            row_m[r] = mx;
            row_c[r] = corr;
        }
        __syncthreads();

        // Rescale running output, then accumulate P @ V
        #pragma unroll
        for (int i = 0; i < 4; i++) {
            float cr = row_c[ty * 4 + i];
            #pragma unroll
            for (int j = 0; j < 4; j++) acc[i][j] *= cr;
        }
        #pragma unroll 8
        for (int kk = 0; kk < 64; kk++) {
            float p[4], v[4];
            #pragma unroll
            for (int i = 0; i < 4; i++) p[i] = Ps[ty * 4 + i][kk];
            #pragma unroll
            for (int j = 0; j < 4; j++) v[j] = Vs[kk][tx * 4 + j];
            #pragma unroll
            for (int i = 0; i < 4; i++)
                #pragma unroll
                for (int j = 0; j < 4; j++)
                    acc[i][j] = fmaf(p[i], v[j], acc[i][j]);
        }
        __syncthreads();
    }

    // Normalize and write ctx in [B,S,D] layout (heads interleaved)
    float* Cg = g_ctx + ((size_t)b * SQ + q0) * DD + h * HD;
    #pragma unroll
    for (int i = 0; i < 4; i++) {
        float inv = 1.0f / row_l[ty * 4 + i];
        #pragma unroll
        for (int j = 0; j < 4; j++)
            Cg[(ty * 4 + i) * DD + tx * 4 + j] = acc[i][j] * inv;
    }
}

// ---------------------------------------------------------------------------
// Output projection: out = ctx @ Wo^T + bo
// ---------------------------------------------------------------------------
__global__ void proj_kernel(const float* __restrict__ Wo,
                            const float* __restrict__ bo,
                            float* __restrict__ out)
{
    gemm_nt_64x64(g_ctx, Wo, bo, out, DD, DD, blockIdx.y * 64, blockIdx.x * 64);
}

// ---------------------------------------------------------------------------
extern "C" void kernel_launch(void* const* d_in, const int* in_sizes, int n_in,
                              void* d_out, int out_size)
{
    const float* x     = (const float*)d_in[0];
    const float* Wq    = (const float*)d_in[1];
    const float* bq    = (const float*)d_in[2];
    const float* Wk    = (const float*)d_in[3];
    const float* bk    = (const float*)d_in[4];
    const float* Wv    = (const float*)d_in[5];
    const float* bv    = (const float*)d_in[6];
    const float* Wo    = (const float*)d_in[7];
    const float* bo    = (const float*)d_in[8];
    const float* amask = (const float*)d_in[9];
    const float* ipa   = (const float*)d_in[10];
    const float* assoc = (const float*)d_in[11];
    const int* cid            = (const int*)d_in[12];       // int32 (JAX x64 off)
    const unsigned char* kpm  = (const unsigned char*)d_in[13];
    float* out = (float*)d_out;

    // attn_kernel needs 67,328 B of dynamic smem (>48KB default)
    cudaFuncSetAttribute(attn_kernel, cudaFuncAttributeMaxDynamicSharedMemorySize, 68 * 1024);

    dim3 tb(16, 16);

    // QKV projections (z selects projection)
    qkv_kernel<<<dim3(DD / 64, (BB * SQ) / 64, 3), tb>>>(x, Wq, bq, Wk, bk, Wv, bv);

    // Combined bias matrix [B,S,S]
    bias_kernel<<<(BB * SQ * SQ) / 256, 256>>>(ipa, assoc, amask, cid, kpm);

    // Fused attention
    attn_kernel<<<dim3(SQ / 64, NH, BB), tb, 4 * 64 * 65 * 4 + 3 * 64 * 4>>>();

    // Output projection
    proj_kernel<<<dim3(DD / 64, (BB * SQ) / 64), tb>>>(Wo, bo, out);
}

// round 5
// speedup vs baseline: 2.2631x; 2.2631x over previous
#include <cuda_runtime.h>
#include <math.h>
#include <stdint.h>

// Problem constants
#define BB 2
#define SQ 2048
#define DD 512
#define NH 8
#define HD 64
#define SCALE 0.125f   // 1/sqrt(64)
#define CBIAS 0.5f

// Scratch (device globals; no allocation allowed)
__device__ float g_Q[BB * SQ * DD];
__device__ float g_K[BB * SQ * DD];
__device__ float g_V[BB * SQ * DD];
__device__ float g_ctx[BB * SQ * DD];
__device__ float g_bias[(size_t)BB * SQ * SQ];

// ---------------------------------------------------------------------------
// TF32 helpers
// ---------------------------------------------------------------------------
__device__ __forceinline__ uint32_t f2tf(float f) {
    uint32_t u;
    asm("cvt.rna.tf32.f32 %0, %1;" : "=r"(u) : "f"(f));
    return u;
}

__device__ __forceinline__ void mma_tf32(float c[4],
    uint32_t a0, uint32_t a1, uint32_t a2, uint32_t a3,
    uint32_t b0, uint32_t b1)
{
    asm volatile(
        "mma.sync.aligned.m16n8k8.row.col.f32.tf32.tf32.f32 "
        "{%0,%1,%2,%3}, {%4,%5,%6,%7}, {%8,%9}, {%0,%1,%2,%3};"
        : "+f"(c[0]), "+f"(c[1]), "+f"(c[2]), "+f"(c[3])
        : "r"(a0), "r"(a1), "r"(a2), "r"(a3), "r"(b0), "r"(b1));
}

// ---------------------------------------------------------------------------
// TF32x3 GEMM: C[M,N] = A[M,K] @ W[N,K]^T + bias[N]
// BM=128, BN=64, BK=32. 256 threads = 8 warps, each warp 16 rows x 64 cols.
// K-tile is 32 wide -> pitch GP=36 (>=32, mod 32 == 4 for conflict-free frags)
// ---------------------------------------------------------------------------
#define GP 36
#define GEMM_SMEM ((128 * GP * 2 + 64 * GP * 2) * 4)

__device__ __forceinline__ void gemm_tc_body(
    const float* __restrict__ A, const float* __restrict__ W,
    const float* __restrict__ bias, float* __restrict__ C,
    int m0, int n0)
{
    extern __shared__ float sm[];
    float* Ahi = sm;                    // 128*GP
    float* Alo = Ahi + 128 * GP;
    float* Whi = Alo + 128 * GP;        // 64*GP
    float* Wlo = Whi + 64 * GP;

    const int tid = threadIdx.x;
    const int w = tid >> 5, lane = tid & 31;
    const int g = lane >> 2, t = lane & 3;

    float acc[8][4] = {};

    for (int k0 = 0; k0 < DD; k0 += 32) {
        // Stage A tile (128x32) as hi/lo tf32
        #pragma unroll
        for (int i = 0; i < 16; i++) {
            int e = tid + i * 256;
            int r = e >> 5, c = e & 31;
            float v = A[(size_t)(m0 + r) * DD + k0 + c];
            uint32_t hb = f2tf(v);
            float hf = __uint_as_float(hb);
            Ahi[r * GP + c] = hf;
            Alo[r * GP + c] = __uint_as_float(f2tf(v - hf));
        }
        // Stage W tile (64x32)
        #pragma unroll
        for (int i = 0; i < 8; i++) {
            int e = tid + i * 256;
            int r = e >> 5, c = e & 31;
            float v = W[(size_t)(n0 + r) * DD + k0 + c];
            uint32_t hb = f2tf(v);
            float hf = __uint_as_float(hb);
            Whi[r * GP + c] = hf;
            Wlo[r * GP + c] = __uint_as_float(f2tf(v - hf));
        }
        __syncthreads();

        #pragma unroll
        for (int kk = 0; kk < 4; kk++) {
            const int ar = w * 16 + g, ac = kk * 8 + t;
            uint32_t ah0 = __float_as_uint(Ahi[ar * GP + ac]);
            uint32_t ah1 = __float_as_uint(Ahi[(ar + 8) * GP + ac]);
            uint32_t ah2 = __float_as_uint(Ahi[ar * GP + ac + 4]);
            uint32_t ah3 = __float_as_uint(Ahi[(ar + 8) * GP + ac + 4]);
            uint32_t al0 = __float_as_uint(Alo[ar * GP + ac]);
            uint32_t al1 = __float_as_uint(Alo[(ar + 8) * GP + ac]);
            uint32_t al2 = __float_as_uint(Alo[ar * GP + ac + 4]);
            uint32_t al3 = __float_as_uint(Alo[(ar + 8) * GP + ac + 4]);
            #pragma unroll
            for (int ns = 0; ns < 8; ns++) {
                const int br = ns * 8 + g, bc = kk * 8 + t;
                uint32_t bh0 = __float_as_uint(Whi[br * GP + bc]);
                uint32_t bh1 = __float_as_uint(Whi[br * GP + bc + 4]);
                uint32_t bl0 = __float_as_uint(Wlo[br * GP + bc]);
                uint32_t bl1 = __float_as_uint(Wlo[br * GP + bc + 4]);
                mma_tf32(acc[ns], ah0, ah1, ah2, ah3, bh0, bh1);  // hi*hi
                mma_tf32(acc[ns], ah0, ah1, ah2, ah3, bl0, bl1);  // hi*lo
                mma_tf32(acc[ns], al0, al1, al2, al3, bh0, bh1);  // lo*hi
            }
        }
        __syncthreads();
    }

    // Epilogue: + bias, write
    #pragma unroll
    for (int ns = 0; ns < 8; ns++) {
        int n = n0 + ns * 8 + 2 * t;
        float b0 = bias[n], b1 = bias[n + 1];
        int r = m0 + w * 16 + g;
        float2 v0 = make_float2(acc[ns][0] + b0, acc[ns][1] + b1);
        float2 v1 = make_float2(acc[ns][2] + b0, acc[ns][3] + b1);
        *(float2*)&C[(size_t)r * DD + n] = v0;
        *(float2*)&C[(size_t)(r + 8) * DD + n] = v1;
    }
}

__global__ __launch_bounds__(256) void qkv_tc_kernel(
    const float* __restrict__ x,
    const float* __restrict__ Wq, const float* __restrict__ bq,
    const float* __restrict__ Wk, const float* __restrict__ bk,
    const float* __restrict__ Wv, const float* __restrict__ bv)
{
    const float* W; const float* bias; float* out;
    if (blockIdx.z == 0)      { W = Wq; bias = bq; out = g_Q; }
    else if (blockIdx.z == 1) { W = Wk; bias = bk; out = g_K; }
    else                      { W = Wv; bias = bv; out = g_V; }
    gemm_tc_body(x, W, bias, out, blockIdx.y * 128, blockIdx.x * 64);
}

__global__ __launch_bounds__(256) void proj_tc_kernel(
    const float* __restrict__ Wo, const float* __restrict__ bo,
    float* __restrict__ out)
{
    gemm_tc_body(g_ctx, Wo, bo, out, blockIdx.y * 128, blockIdx.x * 64);
}

// ---------------------------------------------------------------------------
// Combined additive bias: ipa + assoc + attn_mask + concept + padding
// concept_ids is int32 on device (JAX x64-disabled downcasts int64).
// ---------------------------------------------------------------------------
__global__ void bias_kernel(
    const float* __restrict__ ipa, const float* __restrict__ assoc,
    const float* __restrict__ amask,
    const int* __restrict__ cid, const unsigned char* __restrict__ kpm)
{
    int idx = blockIdx.x * 256 + threadIdx.x;
    int k = idx & (SQ - 1);
    int t = idx >> 11;
    int q = t & (SQ - 1);
    int b = t >> 11;

    int cq = cid[b * SQ + q];
    int ck = cid[b * SQ + k];
    float v = ipa[idx] + assoc[idx] + amask[q * SQ + k];
    if (cq == ck && cq >= 0 && ck >= 0 && q != k) v += CBIAS;
    if (kpm[b * SQ + k]) v = -1e30f;
    g_bias[idx] = v;
}

// ---------------------------------------------------------------------------
// Tensor-core flash attention.
// Q tile = 128 rows, K tile = 64, 8 warps (16 q-rows each).
// QK^T in tf32x3, softmax in registers (quad shfl), PV in tf32 single.
// Tiles are 64 wide -> pitches must be >= 64:
//   KP=68 (mod 32 == 4), VP=72 (mod 32 == 8), PP=68.
// ---------------------------------------------------------------------------
#define KP 68
#define VP 72
#define PP 68
#define ATTN_SMEM ((64 * KP * 2 + 64 * VP + 128 * PP) * 4)

__global__ __launch_bounds__(256, 1) void attn_tc_kernel()
{
    extern __shared__ float sm[];
    float* Khi = sm;                    // 64*KP
    float* Klo = Khi + 64 * KP;
    float* Vs  = Klo + 64 * KP;         // 64*VP
    float* Ps  = Vs + 64 * VP;          // 128*PP

    const int tid = threadIdx.x;
    const int w = tid >> 5, lane = tid & 31;
    const int g = lane >> 2, t = lane & 3;
    const int q0 = blockIdx.x * 128;
    const int h  = blockIdx.y;
    const int b  = blockIdx.z;

    // ---- Stage Q tile into Ps, build persistent A-fragments (hi/lo) ----
    const float* Qg = g_Q + ((size_t)b * SQ + q0) * DD + h * HD;
    #pragma unroll
    for (int i = 0; i < 32; i++) {
        int e = tid + i * 256;          // 0..8191
        int r = e >> 6, c = e & 63;
        Ps[r * PP + c] = Qg[(size_t)r * DD + c];
    }
    __syncthreads();

    uint32_t qh[8][4], ql[8][4];
    #pragma unroll
    for (int kk = 0; kk < 8; kk++) {
        #pragma unroll
        for (int i = 0; i < 4; i++) {
            int r = w * 16 + g + (i & 1) * 8;
            int c = kk * 8 + t + (i >> 1) * 4;
            float v = Ps[r * PP + c] * SCALE;
            uint32_t hb = f2tf(v);
            qh[kk][i] = hb;
            ql[kk][i] = f2tf(v - __uint_as_float(hb));
        }
    }
    __syncthreads();

    float mrow[2] = { -1e30f, -1e30f };   // rows g, g+8 (dup across quad)
    float lrow[2] = { 0.0f, 0.0f };
    float o[8][4] = {};

    const float* Bg = g_bias + ((size_t)b * SQ + q0) * SQ;
    const float* Kbase = g_K + (size_t)b * SQ * DD + h * HD;
    const float* Vbase = g_V + (size_t)b * SQ * DD + h * HD;

    for (int kt = 0; kt < SQ / 64; kt++) {
        const int k0 = kt * 64;
        // Prefetch K/V tile into registers (overlaps barrier wait)
        const float* Kg = Kbase + (size_t)k0 * DD;
        const float* Vg = Vbase + (size_t)k0 * DD;
        float kv[16], vv[16];
        #pragma unroll
        for (int i = 0; i < 16; i++) {
            int e = tid + i * 256;      // 0..4095
            int r = e >> 6, c = e & 63;
            kv[i] = Kg[(size_t)r * DD + c];
            vv[i] = Vg[(size_t)r * DD + c];
        }
        __syncthreads();   // prior iteration's smem reads complete
        #pragma unroll
        for (int i = 0; i < 16; i++) {
            int e = tid + i * 256;
            int r = e >> 6, c = e & 63;
            uint32_t hb = f2tf(kv[i]);
            float hf = __uint_as_float(hb);
            Khi[r * KP + c] = hf;
            Klo[r * KP + c] = __uint_as_float(f2tf(kv[i] - hf));
            Vs[r * VP + c]  = __uint_as_float(f2tf(vv[i]));
        }
        __syncthreads();

        // ---- S = Q @ K^T (tf32x3) ----
        float s[8][4] = {};
        #pragma unroll
        for (int kk = 0; kk < 8; kk++) {
            #pragma unroll
            for (int ns = 0; ns < 8; ns++) {
                const int br = ns * 8 + g, bc = kk * 8 + t;
                uint32_t bh0 = __float_as_uint(Khi[br * KP + bc]);
                uint32_t bh1 = __float_as_uint(Khi[br * KP + bc + 4]);
                uint32_t bl0 = __float_as_uint(Klo[br * KP + bc]);
                uint32_t bl1 = __float_as_uint(Klo[br * KP + bc + 4]);
                mma_tf32(s[ns], qh[kk][0], qh[kk][1], qh[kk][2], qh[kk][3], bh0, bh1);
                mma_tf32(s[ns], qh[kk][0], qh[kk][1], qh[kk][2], qh[kk][3], bl0, bl1);
                mma_tf32(s[ns], ql[kk][0], ql[kk][1], ql[kk][2], ql[kk][3], bh0, bh1);
            }
        }

        // ---- Add combined bias (gmem, L2-resident after head 0) ----
        #pragma unroll
        for (int ns = 0; ns < 8; ns++) {
            int col = k0 + ns * 8 + 2 * t;
            float2 b0v = *(const float2*)&Bg[(size_t)(w * 16 + g) * SQ + col];
            float2 b1v = *(const float2*)&Bg[(size_t)(w * 16 + g + 8) * SQ + col];
            s[ns][0] += b0v.x; s[ns][1] += b0v.y;
            s[ns][2] += b1v.x; s[ns][3] += b1v.y;
        }

        // ---- Online softmax (registers + quad shfl) ----
        float tm0 = -1e30f, tm1 = -1e30f;
        #pragma unroll
        for (int ns = 0; ns < 8; ns++) {
            tm0 = fmaxf(tm0, fmaxf(s[ns][0], s[ns][1]));
            tm1 = fmaxf(tm1, fmaxf(s[ns][2], s[ns][3]));
        }
        tm0 = fmaxf(tm0, __shfl_xor_sync(0xffffffffu, tm0, 1));
        tm0 = fmaxf(tm0, __shfl_xor_sync(0xffffffffu, tm0, 2));
        tm1 = fmaxf(tm1, __shfl_xor_sync(0xffffffffu, tm1, 1));
        tm1 = fmaxf(tm1, __shfl_xor_sync(0xffffffffu, tm1, 2));

        float mn0 = fmaxf(mrow[0], tm0), mn1 = fmaxf(mrow[1], tm1);
        float cr0 = __expf(mrow[0] - mn0), cr1 = __expf(mrow[1] - mn1);
        float sum0 = 0.0f, sum1 = 0.0f;
        const int prow = w * 16 + g;
        #pragma unroll
        for (int ns = 0; ns < 8; ns++) {
            float p0 = __expf(s[ns][0] - mn0);
            float p1 = __expf(s[ns][1] - mn0);
            float p2 = __expf(s[ns][2] - mn1);
            float p3 = __expf(s[ns][3] - mn1);
            sum0 += p0 + p1; sum1 += p2 + p3;
            int pc = ns * 8 + 2 * t;
            Ps[prow * PP + pc]           = __uint_as_float(f2tf(p0));
            Ps[prow * PP + pc + 1]       = __uint_as_float(f2tf(p1));
            Ps[(prow + 8) * PP + pc]     = __uint_as_float(f2tf(p2));
            Ps[(prow + 8) * PP + pc + 1] = __uint_as_float(f2tf(p3));
            o[ns][0] *= cr0; o[ns][1] *= cr0;
            o[ns][2] *= cr1; o[ns][3] *= cr1;
        }
        sum0 += __shfl_xor_sync(0xffffffffu, sum0, 1);
        sum0 += __shfl_xor_sync(0xffffffffu, sum0, 2);
        sum1 += __shfl_xor_sync(0xffffffffu, sum1, 1);
        sum1 += __shfl_xor_sync(0xffffffffu, sum1, 2);
        lrow[0] = lrow[0] * cr0 + sum0;
        lrow[1] = lrow[1] * cr1 + sum1;
        mrow[0] = mn0; mrow[1] = mn1;
        __syncwarp();   // P rows are warp-private; cross-lane visibility only

        // ---- O += P @ V (tf32 single-pass) ----
        #pragma unroll
        for (int kk = 0; kk < 8; kk++) {
            uint32_t a0 = __float_as_uint(Ps[prow * PP + kk * 8 + t]);
            uint32_t a1 = __float_as_uint(Ps[(prow + 8) * PP + kk * 8 + t]);
            uint32_t a2 = __float_as_uint(Ps[prow * PP + kk * 8 + t + 4]);
            uint32_t a3 = __float_as_uint(Ps[(prow + 8) * PP + kk * 8 + t + 4]);
            #pragma unroll
            for (int ns = 0; ns < 8; ns++) {
                uint32_t b0 = __float_as_uint(Vs[(kk * 8 + t) * VP + ns * 8 + g]);
                uint32_t b1 = __float_as_uint(Vs[(kk * 8 + t + 4) * VP + ns * 8 + g]);
                mma_tf32(o[ns], a0, a1, a2, a3, b0, b1);
            }
        }
    }

    // ---- Normalize + write ctx ----
    float inv0 = 1.0f / lrow[0], inv1 = 1.0f / lrow[1];
    float* Cg = g_ctx + ((size_t)b * SQ + q0) * DD + h * HD;
    #pragma unroll
    for (int ns = 0; ns < 8; ns++) {
        int col = ns * 8 + 2 * t;
        float2 v0 = make_float2(o[ns][0] * inv0, o[ns][1] * inv0);
        float2 v1 = make_float2(o[ns][2] * inv1, o[ns][3] * inv1);
        *(float2*)&Cg[(size_t)(w * 16 + g) * DD + col] = v0;
        *(float2*)&Cg[(size_t)(w * 16 + g + 8) * DD + col] = v1;
    }
}

// ---------------------------------------------------------------------------
extern "C" void kernel_launch(void* const* d_in, const int* in_sizes, int n_in,
                              void* d_out, int out_size)
{
    const float* x     = (const float*)d_in[0];
    const float* Wq    = (const float*)d_in[1];
    const float* bq    = (const float*)d_in[2];
    const float* Wk    = (const float*)d_in[3];
    const float* bk    = (const float*)d_in[4];
    const float* Wv    = (const float*)d_in[5];
    const float* bv    = (const float*)d_in[6];
    const float* Wo    = (const float*)d_in[7];
    const float* bo    = (const float*)d_in[8];
    const float* amask = (const float*)d_in[9];
    const float* ipa   = (const float*)d_in[10];
    const float* assoc = (const float*)d_in[11];
    const int* cid            = (const int*)d_in[12];       // int32 (JAX x64 off)
    const unsigned char* kpm  = (const unsigned char*)d_in[13];
    float* out = (float*)d_out;

    cudaFuncSetAttribute(qkv_tc_kernel,  cudaFuncAttributeMaxDynamicSharedMemorySize, GEMM_SMEM);
    cudaFuncSetAttribute(proj_tc_kernel, cudaFuncAttributeMaxDynamicSharedMemorySize, GEMM_SMEM);
    cudaFuncSetAttribute(attn_tc_kernel, cudaFuncAttributeMaxDynamicSharedMemorySize, ATTN_SMEM);

    // QKV projections: tf32x3 tensor-core GEMM
    qkv_tc_kernel<<<dim3(DD / 64, (BB * SQ) / 128, 3), 256, GEMM_SMEM>>>(
        x, Wq, bq, Wk, bk, Wv, bv);

    // Combined bias matrix [B,S,S]
    bias_kernel<<<(BB * SQ * SQ) / 256, 256>>>(ipa, assoc, amask, cid, kpm);

    // Tensor-core flash attention
    attn_tc_kernel<<<dim3(SQ / 128, NH, BB), 256, ATTN_SMEM>>>();

    // Output projection
    proj_tc_kernel<<<dim3(DD / 64, (BB * SQ) / 128), 256, GEMM_SMEM>>>(Wo, bo, out);
}

// round 6
// speedup vs baseline: 3.2291x; 1.4268x over previous
#include <cuda_runtime.h>
#include <math.h>
#include <stdint.h>

// Problem constants
#define BB 2
#define SQ 2048
#define DD 512
#define NH 8
#define HD 64
#define SCALE 0.125f   // 1/sqrt(64)
#define CBIAS 0.5f

// Scratch (device globals; no allocation allowed)
__device__ float g_Q[BB * SQ * DD];
__device__ float g_K[BB * SQ * DD];
__device__ float g_V[BB * SQ * DD];
__device__ float g_ctx[BB * SQ * DD];
__device__ float g_bias[(size_t)BB * SQ * SQ];

// ---------------------------------------------------------------------------
// Precision helpers
// ---------------------------------------------------------------------------
__device__ __forceinline__ uint32_t f2tf(float f) {
    uint32_t u;
    asm("cvt.rna.tf32.f32 %0, %1;" : "=r"(u) : "f"(f));
    return u;
}

// Pack two floats into bf16x2: lo element in bits[15:0], hi element in [31:16]
__device__ __forceinline__ uint32_t pack_bf2(float e0, float e1) {
    uint32_t r;
    asm("cvt.rn.bf16x2.f32 %0, %1, %2;" : "=r"(r) : "f"(e1), "f"(e0));
    return r;
}
__device__ __forceinline__ float bf2_lo_f(uint32_t p) { return __uint_as_float(p << 16); }
__device__ __forceinline__ float bf2_hi_f(uint32_t p) { return __uint_as_float(p & 0xffff0000u); }

// Split a float pair into bf16 hi + bf16 residual-lo packed words
__device__ __forceinline__ void split_bf2(float x, float y, uint32_t& hi, uint32_t& lo) {
    hi = pack_bf2(x, y);
    lo = pack_bf2(x - bf2_lo_f(hi), y - bf2_hi_f(hi));
}

__device__ __forceinline__ void mma_bf16(float c[4],
    uint32_t a0, uint32_t a1, uint32_t a2, uint32_t a3,
    uint32_t b0, uint32_t b1)
{
    asm volatile(
        "mma.sync.aligned.m16n8k16.row.col.f32.bf16.bf16.f32 "
        "{%0,%1,%2,%3}, {%4,%5,%6,%7}, {%8,%9}, {%0,%1,%2,%3};"
        : "+f"(c[0]), "+f"(c[1]), "+f"(c[2]), "+f"(c[3])
        : "r"(a0), "r"(a1), "r"(a2), "r"(a3), "r"(b0), "r"(b1));
}

__device__ __forceinline__ void mma_tf32(float c[4],
    uint32_t a0, uint32_t a1, uint32_t a2, uint32_t a3,
    uint32_t b0, uint32_t b1)
{
    asm volatile(
        "mma.sync.aligned.m16n8k8.row.col.f32.tf32.tf32.f32 "
        "{%0,%1,%2,%3}, {%4,%5,%6,%7}, {%8,%9}, {%0,%1,%2,%3};"
        : "+f"(c[0]), "+f"(c[1]), "+f"(c[2]), "+f"(c[3])
        : "r"(a0), "r"(a1), "r"(a2), "r"(a3), "r"(b0), "r"(b1));
}

// ---------------------------------------------------------------------------
// bf16x3 GEMM: C[M,N] = A[M,K] @ W[N,K]^T + bias[N]
// BM=128, BN=64, BK=32 (2 k16 steps). 256 threads = 8 warps, warp = 16r x 64c.
// smem holds bf16x2 words: 16 words per 32-float row; pitch AP=20 (20%32==20,
// frag reads hit g*20 mod 32 = multiples of 4, all distinct -> conflict-free).
// ---------------------------------------------------------------------------
#define AP 20
#define GEMM_SMEM ((128 * AP * 2 + 64 * AP * 2) * 4)

__device__ __forceinline__ void gemm_tc_body(
    const float* __restrict__ A, const float* __restrict__ W,
    const float* __restrict__ bias, float* __restrict__ C,
    int m0, int n0)
{
    extern __shared__ uint32_t smu[];
    uint32_t* Ahi = smu;                  // 128*AP words
    uint32_t* Alo = Ahi + 128 * AP;
    uint32_t* Whi = Alo + 128 * AP;       // 64*AP words
    uint32_t* Wlo = Whi + 64 * AP;

    const int tid = threadIdx.x;
    const int w = tid >> 5, lane = tid & 31;
    const int g = lane >> 2, t = lane & 3;

    float acc[8][4] = {};

    for (int k0 = 0; k0 < DD; k0 += 32) {
        // Stage A tile (128x32 floats -> 128x16 words)
        #pragma unroll
        for (int i = 0; i < 8; i++) {
            int e = tid + i * 256;        // 0..2047
            int r = e >> 4, c2 = e & 15;
            float2 v = *(const float2*)&A[(size_t)(m0 + r) * DD + k0 + 2 * c2];
            split_bf2(v.x, v.y, Ahi[r * AP + c2], Alo[r * AP + c2]);
        }
        // Stage W tile (64x32 -> 64x16 words)
        #pragma unroll
        for (int i = 0; i < 4; i++) {
            int e = tid + i * 256;        // 0..1023
            int r = e >> 4, c2 = e & 15;
            float2 v = *(const float2*)&W[(size_t)(n0 + r) * DD + k0 + 2 * c2];
            split_bf2(v.x, v.y, Whi[r * AP + c2], Wlo[r * AP + c2]);
        }
        __syncthreads();

        #pragma unroll
        for (int kk = 0; kk < 2; kk++) {
            const int ar = w * 16 + g, ac = kk * 8 + t;
            uint32_t ah0 = Ahi[ar * AP + ac];
            uint32_t ah1 = Ahi[(ar + 8) * AP + ac];
            uint32_t ah2 = Ahi[ar * AP + ac + 4];
            uint32_t ah3 = Ahi[(ar + 8) * AP + ac + 4];
            uint32_t al0 = Alo[ar * AP + ac];
            uint32_t al1 = Alo[(ar + 8) * AP + ac];
            uint32_t al2 = Alo[ar * AP + ac + 4];
            uint32_t al3 = Alo[(ar + 8) * AP + ac + 4];
            #pragma unroll
            for (int ns = 0; ns < 8; ns++) {
                const int br = ns * 8 + g, bc = kk * 8 + t;
                uint32_t bh0 = Whi[br * AP + bc];
                uint32_t bh1 = Whi[br * AP + bc + 4];
                uint32_t bl0 = Wlo[br * AP + bc];
                uint32_t bl1 = Wlo[br * AP + bc + 4];
                mma_bf16(acc[ns], ah0, ah1, ah2, ah3, bh0, bh1);  // hi*hi
                mma_bf16(acc[ns], ah0, ah1, ah2, ah3, bl0, bl1);  // hi*lo
                mma_bf16(acc[ns], al0, al1, al2, al3, bh0, bh1);  // lo*hi
            }
        }
        __syncthreads();
    }

    // Epilogue: + bias, write
    #pragma unroll
    for (int ns = 0; ns < 8; ns++) {
        int n = n0 + ns * 8 + 2 * t;
        float b0 = bias[n], b1 = bias[n + 1];
        int r = m0 + w * 16 + g;
        float2 v0 = make_float2(acc[ns][0] + b0, acc[ns][1] + b1);
        float2 v1 = make_float2(acc[ns][2] + b0, acc[ns][3] + b1);
        *(float2*)&C[(size_t)r * DD + n] = v0;
        *(float2*)&C[(size_t)(r + 8) * DD + n] = v1;
    }
}

__global__ __launch_bounds__(256) void qkv_tc_kernel(
    const float* __restrict__ x,
    const float* __restrict__ Wq, const float* __restrict__ bq,
    const float* __restrict__ Wk, const float* __restrict__ bk,
    const float* __restrict__ Wv, const float* __restrict__ bv)
{
    const float* W; const float* bias; float* out;
    if (blockIdx.z == 0)      { W = Wq; bias = bq; out = g_Q; }
    else if (blockIdx.z == 1) { W = Wk; bias = bk; out = g_K; }
    else                      { W = Wv; bias = bv; out = g_V; }
    gemm_tc_body(x, W, bias, out, blockIdx.y * 128, blockIdx.x * 64);
}

__global__ __launch_bounds__(256) void proj_tc_kernel(
    const float* __restrict__ Wo, const float* __restrict__ bo,
    float* __restrict__ out)
{
    gemm_tc_body(g_ctx, Wo, bo, out, blockIdx.y * 128, blockIdx.x * 64);
}

// ---------------------------------------------------------------------------
// Combined additive bias: ipa + assoc + attn_mask + concept + padding
// concept_ids is int32 on device (JAX x64-disabled downcasts int64).
// ---------------------------------------------------------------------------
__global__ void bias_kernel(
    const float* __restrict__ ipa, const float* __restrict__ assoc,
    const float* __restrict__ amask,
    const int* __restrict__ cid, const unsigned char* __restrict__ kpm)
{
    int idx = blockIdx.x * 256 + threadIdx.x;
    int k = idx & (SQ - 1);
    int t = idx >> 11;
    int q = t & (SQ - 1);
    int b = t >> 11;

    int cq = cid[b * SQ + q];
    int ck = cid[b * SQ + k];
    float v = ipa[idx] + assoc[idx] + amask[q * SQ + k];
    if (cq == ck && cq >= 0 && ck >= 0 && q != k) v += CBIAS;
    if (kpm[b * SQ + k]) v = -1e30f;
    g_bias[idx] = v;
}

// ---------------------------------------------------------------------------
// Tensor-core flash attention.
// Q tile = 128 rows, K tile = 64, 8 warps (16 q-rows each).
// QK^T in bf16x3 (m16n8k16), softmax in registers, PV in tf32 single-pass.
// K stored as bf16x2 words: 32 words/row, pitch KP=36 (36%32==4, frag-safe).
// V (tf32 floats) pitch VP=72; P/Q staging pitch PP=68.
// ---------------------------------------------------------------------------
#define KP 36
#define VP 72
#define PP 68
#define ATTN_SMEM ((64 * KP * 2 + 64 * VP + 128 * PP) * 4)

__global__ __launch_bounds__(256, 1) void attn_tc_kernel()
{
    extern __shared__ uint32_t smu[];
    uint32_t* Khi = smu;                      // 64*KP words
    uint32_t* Klo = Khi + 64 * KP;
    float* Vs = (float*)(Klo + 64 * KP);      // 64*VP floats
    float* Ps = Vs + 64 * VP;                 // 128*PP floats

    const int tid = threadIdx.x;
    const int w = tid >> 5, lane = tid & 31;
    const int g = lane >> 2, t = lane & 3;
    const int q0 = blockIdx.x * 128;
    const int h  = blockIdx.y;
    const int b  = blockIdx.z;

    // ---- Stage Q tile into Ps, build persistent bf16 A-fragments ----
    const float* Qg = g_Q + ((size_t)b * SQ + q0) * DD + h * HD;
    #pragma unroll
    for (int i = 0; i < 32; i++) {
        int e = tid + i * 256;          // 0..8191
        int r = e >> 6, c = e & 63;
        Ps[r * PP + c] = Qg[(size_t)r * DD + c];
    }
    __syncthreads();

    uint32_t qh[4][4], ql[4][4];
    #pragma unroll
    for (int kk = 0; kk < 4; kk++) {
        #pragma unroll
        for (int i = 0; i < 4; i++) {
            int r = w * 16 + g + (i & 1) * 8;
            int c = kk * 16 + 2 * t + (i >> 1) * 8;
            float x = Ps[r * PP + c] * SCALE;
            float y = Ps[r * PP + c + 1] * SCALE;
            split_bf2(x, y, qh[kk][i], ql[kk][i]);
        }
    }
    __syncthreads();

    float mrow[2] = { -1e30f, -1e30f };   // rows g, g+8 (dup across quad)
    float lrow[2] = { 0.0f, 0.0f };
    float o[8][4] = {};

    const float* Bg = g_bias + ((size_t)b * SQ + q0) * SQ;
    const float* Kbase = g_K + (size_t)b * SQ * DD + h * HD;
    const float* Vbase = g_V + (size_t)b * SQ * DD + h * HD;

    for (int kt = 0; kt < SQ / 64; kt++) {
        const int k0 = kt * 64;
        // Prefetch K/V tile into registers (overlaps barrier wait)
        const float* Kg = Kbase + (size_t)k0 * DD;
        const float* Vg = Vbase + (size_t)k0 * DD;
        float2 kv2[8]; float vv[16];
        #pragma unroll
        for (int i = 0; i < 8; i++) {
            int e = tid + i * 256;      // 0..2047 (word index)
            int r = e >> 5, c2 = e & 31;
            kv2[i] = *(const float2*)&Kg[(size_t)r * DD + 2 * c2];
        }
        #pragma unroll
        for (int i = 0; i < 16; i++) {
            int e = tid + i * 256;      // 0..4095
            int r = e >> 6, c = e & 63;
            vv[i] = Vg[(size_t)r * DD + c];
        }
        __syncthreads();   // prior iteration's smem reads complete
        #pragma unroll
        for (int i = 0; i < 8; i++) {
            int e = tid + i * 256;
            int r = e >> 5, c2 = e & 31;
            split_bf2(kv2[i].x, kv2[i].y, Khi[r * KP + c2], Klo[r * KP + c2]);
        }
        #pragma unroll
        for (int i = 0; i < 16; i++) {
            int e = tid + i * 256;
            int r = e >> 6, c = e & 63;
            Vs[r * VP + c] = __uint_as_float(f2tf(vv[i]));
        }
        __syncthreads();

        // ---- S = Q @ K^T (bf16x3, m16n8k16) ----
        float s[8][4] = {};
        #pragma unroll
        for (int kk = 0; kk < 4; kk++) {
            #pragma unroll
            for (int ns = 0; ns < 8; ns++) {
                const int br = ns * 8 + g, bc = kk * 8 + t;
                uint32_t bh0 = Khi[br * KP + bc];
                uint32_t bh1 = Khi[br * KP + bc + 4];
                uint32_t bl0 = Klo[br * KP + bc];
                uint32_t bl1 = Klo[br * KP + bc + 4];
                mma_bf16(s[ns], qh[kk][0], qh[kk][1], qh[kk][2], qh[kk][3], bh0, bh1);
                mma_bf16(s[ns], qh[kk][0], qh[kk][1], qh[kk][2], qh[kk][3], bl0, bl1);
                mma_bf16(s[ns], ql[kk][0], ql[kk][1], ql[kk][2], ql[kk][3], bh0, bh1);
            }
        }

        // ---- Add combined bias (gmem, L2-resident after head 0) ----
        #pragma unroll
        for (int ns = 0; ns < 8; ns++) {
            int col = k0 + ns * 8 + 2 * t;
            float2 b0v = *(const float2*)&Bg[(size_t)(w * 16 + g) * SQ + col];
            float2 b1v = *(const float2*)&Bg[(size_t)(w * 16 + g + 8) * SQ + col];
            s[ns][0] += b0v.x; s[ns][1] += b0v.y;
            s[ns][2] += b1v.x; s[ns][3] += b1v.y;
        }

        // ---- Online softmax (registers + quad shfl) ----
        float tm0 = -1e30f, tm1 = -1e30f;
        #pragma unroll
        for (int ns = 0; ns < 8; ns++) {
            tm0 = fmaxf(tm0, fmaxf(s[ns][0], s[ns][1]));
            tm1 = fmaxf(tm1, fmaxf(s[ns][2], s[ns][3]));
        }
        tm0 = fmaxf(tm0, __shfl_xor_sync(0xffffffffu, tm0, 1));
        tm0 = fmaxf(tm0, __shfl_xor_sync(0xffffffffu, tm0, 2));
        tm1 = fmaxf(tm1, __shfl_xor_sync(0xffffffffu, tm1, 1));
        tm1 = fmaxf(tm1, __shfl_xor_sync(0xffffffffu, tm1, 2));

        float mn0 = fmaxf(mrow[0], tm0), mn1 = fmaxf(mrow[1], tm1);
        float cr0 = __expf(mrow[0] - mn0), cr1 = __expf(mrow[1] - mn1);
        float sum0 = 0.0f, sum1 = 0.0f;
        const int prow = w * 16 + g;
        #pragma unroll
        for (int ns = 0; ns < 8; ns++) {
            float p0 = __expf(s[ns][0] - mn0);
            float p1 = __expf(s[ns][1] - mn0);
            float p2 = __expf(s[ns][2] - mn1);
            float p3 = __expf(s[ns][3] - mn1);
            sum0 += p0 + p1; sum1 += p2 + p3;
            int pc = ns * 8 + 2 * t;
            Ps[prow * PP + pc]           = __uint_as_float(f2tf(p0));
            Ps[prow * PP + pc + 1]       = __uint_as_float(f2tf(p1));
            Ps[(prow + 8) * PP + pc]     = __uint_as_float(f2tf(p2));
            Ps[(prow + 8) * PP + pc + 1] = __uint_as_float(f2tf(p3));
            o[ns][0] *= cr0; o[ns][1] *= cr0;
            o[ns][2] *= cr1; o[ns][3] *= cr1;
        }
        sum0 += __shfl_xor_sync(0xffffffffu, sum0, 1);
        sum0 += __shfl_xor_sync(0xffffffffu, sum0, 2);
        sum1 += __shfl_xor_sync(0xffffffffu, sum1, 1);
        sum1 += __shfl_xor_sync(0xffffffffu, sum1, 2);
        lrow[0] = lrow[0] * cr0 + sum0;
        lrow[1] = lrow[1] * cr1 + sum1;
        mrow[0] = mn0; mrow[1] = mn1;
        __syncwarp();   // P rows are warp-private; cross-lane visibility only

        // ---- O += P @ V (tf32 single-pass) ----
        #pragma unroll
        for (int kk = 0; kk < 8; kk++) {
            uint32_t a0 = __float_as_uint(Ps[prow * PP + kk * 8 + t]);
            uint32_t a1 = __float_as_uint(Ps[(prow + 8) * PP + kk * 8 + t]);
            uint32_t a2 = __float_as_uint(Ps[prow * PP + kk * 8 + t + 4]);
            uint32_t a3 = __float_as_uint(Ps[(prow + 8) * PP + kk * 8 + t + 4]);
            #pragma unroll
            for (int ns = 0; ns < 8; ns++) {
                uint32_t b0 = __float_as_uint(Vs[(kk * 8 + t) * VP + ns * 8 + g]);
                uint32_t b1 = __float_as_uint(Vs[(kk * 8 + t + 4) * VP + ns * 8 + g]);
                mma_tf32(o[ns], a0, a1, a2, a3, b0, b1);
            }
        }
    }

    // ---- Normalize + write ctx ----
    float inv0 = 1.0f / lrow[0], inv1 = 1.0f / lrow[1];
    float* Cg = g_ctx + ((size_t)b * SQ + q0) * DD + h * HD;
    #pragma unroll
    for (int ns = 0; ns < 8; ns++) {
        int col = ns * 8 + 2 * t;
        float2 v0 = make_float2(o[ns][0] * inv0, o[ns][1] * inv0);
        float2 v1 = make_float2(o[ns][2] * inv1, o[ns][3] * inv1);
        *(float2*)&Cg[(size_t)(w * 16 + g) * DD + col] = v0;
        *(float2*)&Cg[(size_t)(w * 16 + g + 8) * DD + col] = v1;
    }
}

// ---------------------------------------------------------------------------
extern "C" void kernel_launch(void* const* d_in, const int* in_sizes, int n_in,
                              void* d_out, int out_size)
{
    const float* x     = (const float*)d_in[0];
    const float* Wq    = (const float*)d_in[1];
    const float* bq    = (const float*)d_in[2];
    const float* Wk    = (const float*)d_in[3];
    const float* bk    = (const float*)d_in[4];
    const float* Wv    = (const float*)d_in[5];
    const float* bv    = (const float*)d_in[6];
    const float* Wo    = (const float*)d_in[7];
    const float* bo    = (const float*)d_in[8];
    const float* amask = (const float*)d_in[9];
    const float* ipa   = (const float*)d_in[10];
    const float* assoc = (const float*)d_in[11];
    const int* cid            = (const int*)d_in[12];       // int32 (JAX x64 off)
    const unsigned char* kpm  = (const unsigned char*)d_in[13];
    float* out = (float*)d_out;

    cudaFuncSetAttribute(attn_tc_kernel, cudaFuncAttributeMaxDynamicSharedMemorySize, ATTN_SMEM);

    // QKV projections: bf16x3 tensor-core GEMM
    qkv_tc_kernel<<<dim3(DD / 64, (BB * SQ) / 128, 3), 256, GEMM_SMEM>>>(
        x, Wq, bq, Wk, bk, Wv, bv);

    // Combined bias matrix [B,S,S]
    bias_kernel<<<(BB * SQ * SQ) / 256, 256>>>(ipa, assoc, amask, cid, kpm);

    // Tensor-core flash attention
    attn_tc_kernel<<<dim3(SQ / 128, NH, BB), 256, ATTN_SMEM>>>();

    // Output projection
    proj_tc_kernel<<<dim3(DD / 64, (BB * SQ) / 128), 256, GEMM_SMEM>>>(Wo, bo, out);
}

// round 7
// speedup vs baseline: 3.6133x; 1.1190x over previous
#include <cuda_runtime.h>
#include <math.h>
#include <stdint.h>

// Problem constants
#define BB 2
#define SQ 2048
#define DD 512
#define NH 8
#define HD 64
#define SCALE 0.125f   // 1/sqrt(64)
#define CBIAS 0.5f

// Scratch (device globals; no allocation allowed)
__device__ float g_Q[BB * SQ * DD];
__device__ float g_K[BB * SQ * DD];
__device__ float g_V[BB * SQ * DD];
__device__ float g_ctx[BB * SQ * DD];
__device__ float g_bias[(size_t)BB * SQ * SQ];

// ---------------------------------------------------------------------------
// Precision helpers
// ---------------------------------------------------------------------------
__device__ __forceinline__ uint32_t f2tf(float f) {
    uint32_t u;
    asm("cvt.rna.tf32.f32 %0, %1;" : "=r"(u) : "f"(f));
    return u;
}

// Pack two floats into bf16x2: lo element in bits[15:0], hi element in [31:16]
__device__ __forceinline__ uint32_t pack_bf2(float e0, float e1) {
    uint32_t r;
    asm("cvt.rn.bf16x2.f32 %0, %1, %2;" : "=r"(r) : "f"(e1), "f"(e0));
    return r;
}
__device__ __forceinline__ float bf2_lo_f(uint32_t p) { return __uint_as_float(p << 16); }
__device__ __forceinline__ float bf2_hi_f(uint32_t p) { return __uint_as_float(p & 0xffff0000u); }

// Split a float pair into bf16 hi + bf16 residual-lo packed words
__device__ __forceinline__ void split_bf2(float x, float y, uint32_t& hi, uint32_t& lo) {
    hi = pack_bf2(x, y);
    lo = pack_bf2(x - bf2_lo_f(hi), y - bf2_hi_f(hi));
}

__device__ __forceinline__ void mma_bf16(float c[4],
    uint32_t a0, uint32_t a1, uint32_t a2, uint32_t a3,
    uint32_t b0, uint32_t b1)
{
    asm volatile(
        "mma.sync.aligned.m16n8k16.row.col.f32.bf16.bf16.f32 "
        "{%0,%1,%2,%3}, {%4,%5,%6,%7}, {%8,%9}, {%0,%1,%2,%3};"
        : "+f"(c[0]), "+f"(c[1]), "+f"(c[2]), "+f"(c[3])
        : "r"(a0), "r"(a1), "r"(a2), "r"(a3), "r"(b0), "r"(b1));
}

__device__ __forceinline__ void mma_tf32(float c[4],
    uint32_t a0, uint32_t a1, uint32_t a2, uint32_t a3,
    uint32_t b0, uint32_t b1)
{
    asm volatile(
        "mma.sync.aligned.m16n8k8.row.col.f32.tf32.tf32.f32 "
        "{%0,%1,%2,%3}, {%4,%5,%6,%7}, {%8,%9}, {%0,%1,%2,%3};"
        : "+f"(c[0]), "+f"(c[1]), "+f"(c[2]), "+f"(c[3])
        : "r"(a0), "r"(a1), "r"(a2), "r"(a3), "r"(b0), "r"(b1));
}

// ---------------------------------------------------------------------------
// bf16x3 GEMM: C[M,N] = A[M,K] @ W[N,K]^T + bias[N]
// BM=128, BN=64, BK=32 (2 k16 steps). 256 threads = 8 warps, warp = 16r x 64c.
// Register double-buffering: next k-tile loaded into regs during compute.
// ---------------------------------------------------------------------------
#define AP 20
#define GEMM_SMEM ((128 * AP * 2 + 64 * AP * 2) * 4)

__device__ __forceinline__ void gemm_tc_body(
    const float* __restrict__ A, const float* __restrict__ W,
    const float* __restrict__ bias, float* __restrict__ C,
    int m0, int n0)
{
    extern __shared__ uint32_t smu[];
    uint32_t* Ahi = smu;                  // 128*AP words
    uint32_t* Alo = Ahi + 128 * AP;
    uint32_t* Whi = Alo + 128 * AP;       // 64*AP words
    uint32_t* Wlo = Whi + 64 * AP;

    const int tid = threadIdx.x;
    const int w = tid >> 5, lane = tid & 31;
    const int g = lane >> 2, t = lane & 3;

    float acc[8][4] = {};
    float2 pa[8], pw[4];

    // Preload k0 = 0 tiles into registers
    #pragma unroll
    for (int i = 0; i < 8; i++) {
        int e = tid + i * 256;
        int r = e >> 4, c2 = e & 15;
        pa[i] = *(const float2*)&A[(size_t)(m0 + r) * DD + 2 * c2];
    }
    #pragma unroll
    for (int i = 0; i < 4; i++) {
        int e = tid + i * 256;
        int r = e >> 4, c2 = e & 15;
        pw[i] = *(const float2*)&W[(size_t)(n0 + r) * DD + 2 * c2];
    }

    for (int k0 = 0; k0 < DD; k0 += 32) {
        // Convert staged registers into smem
        #pragma unroll
        for (int i = 0; i < 8; i++) {
            int e = tid + i * 256;
            int r = e >> 4, c2 = e & 15;
            split_bf2(pa[i].x, pa[i].y, Ahi[r * AP + c2], Alo[r * AP + c2]);
        }
        #pragma unroll
        for (int i = 0; i < 4; i++) {
            int e = tid + i * 256;
            int r = e >> 4, c2 = e & 15;
            split_bf2(pw[i].x, pw[i].y, Whi[r * AP + c2], Wlo[r * AP + c2]);
        }
        __syncthreads();

        // Prefetch next k-tile (overlaps with MMA compute below)
        if (k0 + 32 < DD) {
            #pragma unroll
            for (int i = 0; i < 8; i++) {
                int e = tid + i * 256;
                int r = e >> 4, c2 = e & 15;
                pa[i] = *(const float2*)&A[(size_t)(m0 + r) * DD + k0 + 32 + 2 * c2];
            }
            #pragma unroll
            for (int i = 0; i < 4; i++) {
                int e = tid + i * 256;
                int r = e >> 4, c2 = e & 15;
                pw[i] = *(const float2*)&W[(size_t)(n0 + r) * DD + k0 + 32 + 2 * c2];
            }
        }

        #pragma unroll
        for (int kk = 0; kk < 2; kk++) {
            const int ar = w * 16 + g, ac = kk * 8 + t;
            uint32_t ah0 = Ahi[ar * AP + ac];
            uint32_t ah1 = Ahi[(ar + 8) * AP + ac];
            uint32_t ah2 = Ahi[ar * AP + ac + 4];
            uint32_t ah3 = Ahi[(ar + 8) * AP + ac + 4];
            uint32_t al0 = Alo[ar * AP + ac];
            uint32_t al1 = Alo[(ar + 8) * AP + ac];
            uint32_t al2 = Alo[ar * AP + ac + 4];
            uint32_t al3 = Alo[(ar + 8) * AP + ac + 4];
            #pragma unroll
            for (int ns = 0; ns < 8; ns++) {
                const int br = ns * 8 + g, bc = kk * 8 + t;
                uint32_t bh0 = Whi[br * AP + bc];
                uint32_t bh1 = Whi[br * AP + bc + 4];
                uint32_t bl0 = Wlo[br * AP + bc];
                uint32_t bl1 = Wlo[br * AP + bc + 4];
                mma_bf16(acc[ns], ah0, ah1, ah2, ah3, bh0, bh1);  // hi*hi
                mma_bf16(acc[ns], ah0, ah1, ah2, ah3, bl0, bl1);  // hi*lo
                mma_bf16(acc[ns], al0, al1, al2, al3, bh0, bh1);  // lo*hi
            }
        }
        __syncthreads();
    }

    // Epilogue: + bias, write
    #pragma unroll
    for (int ns = 0; ns < 8; ns++) {
        int n = n0 + ns * 8 + 2 * t;
        float b0 = bias[n], b1 = bias[n + 1];
        int r = m0 + w * 16 + g;
        float2 v0 = make_float2(acc[ns][0] + b0, acc[ns][1] + b1);
        float2 v1 = make_float2(acc[ns][2] + b0, acc[ns][3] + b1);
        *(float2*)&C[(size_t)r * DD + n] = v0;
        *(float2*)&C[(size_t)(r + 8) * DD + n] = v1;
    }
}

__global__ __launch_bounds__(256) void qkv_tc_kernel(
    const float* __restrict__ x,
    const float* __restrict__ Wq, const float* __restrict__ bq,
    const float* __restrict__ Wk, const float* __restrict__ bk,
    const float* __restrict__ Wv, const float* __restrict__ bv)
{
    const float* W; const float* bias; float* out;
    if (blockIdx.z == 0)      { W = Wq; bias = bq; out = g_Q; }
    else if (blockIdx.z == 1) { W = Wk; bias = bk; out = g_K; }
    else                      { W = Wv; bias = bv; out = g_V; }
    gemm_tc_body(x, W, bias, out, blockIdx.y * 128, blockIdx.x * 64);
}

__global__ __launch_bounds__(256) void proj_tc_kernel(
    const float* __restrict__ Wo, const float* __restrict__ bo,
    float* __restrict__ out)
{
    gemm_tc_body(g_ctx, Wo, bo, out, blockIdx.y * 128, blockIdx.x * 64);
}

// ---------------------------------------------------------------------------
// Combined additive bias: ipa + assoc + attn_mask + concept + padding
// concept_ids is int32 on device (JAX x64-disabled downcasts int64).
// ---------------------------------------------------------------------------
__global__ void bias_kernel(
    const float* __restrict__ ipa, const float* __restrict__ assoc,
    const float* __restrict__ amask,
    const int* __restrict__ cid, const unsigned char* __restrict__ kpm)
{
    int idx = blockIdx.x * 256 + threadIdx.x;
    int k = idx & (SQ - 1);
    int t = idx >> 11;
    int q = t & (SQ - 1);
    int b = t >> 11;

    int cq = cid[b * SQ + q];
    int ck = cid[b * SQ + k];
    float v = ipa[idx] + assoc[idx] + amask[q * SQ + k];
    if (cq == ck && cq >= 0 && ck >= 0 && q != k) v += CBIAS;
    if (kpm[b * SQ + k]) v = -1e30f;
    g_bias[idx] = v;
}

// ---------------------------------------------------------------------------
// Tensor-core flash attention. 2 CTAs/SM co-residency: one CTA's softmax /
// gmem loads overlap the other's MMAs.
// Q tile = 128 rows, K tile = 64, 8 warps (16 q-rows each).
// QK^T in bf16x3 (m16n8k16), softmax in registers, PV in tf32 single-pass.
// ---------------------------------------------------------------------------
#define KP 36
#define VP 72
#define PP 68
#define ATTN_SMEM ((64 * KP * 2 + 64 * VP + 128 * PP) * 4)

__global__ __launch_bounds__(256, 2) void attn_tc_kernel()
{
    extern __shared__ uint32_t smu[];
    uint32_t* Khi = smu;                      // 64*KP words
    uint32_t* Klo = Khi + 64 * KP;
    float* Vs = (float*)(Klo + 64 * KP);      // 64*VP floats
    float* Ps = Vs + 64 * VP;                 // 128*PP floats

    const int tid = threadIdx.x;
    const int w = tid >> 5, lane = tid & 31;
    const int g = lane >> 2, t = lane & 3;
    const int q0 = blockIdx.x * 128;
    const int h  = blockIdx.y;
    const int b  = blockIdx.z;

    // ---- Stage Q tile into Ps, build persistent bf16 A-fragments ----
    const float* Qg = g_Q + ((size_t)b * SQ + q0) * DD + h * HD;
    #pragma unroll
    for (int i = 0; i < 32; i++) {
        int e = tid + i * 256;          // 0..8191
        int r = e >> 6, c = e & 63;
        Ps[r * PP + c] = Qg[(size_t)r * DD + c];
    }
    __syncthreads();

    uint32_t qh[4][4], ql[4][4];
    #pragma unroll
    for (int kk = 0; kk < 4; kk++) {
        #pragma unroll
        for (int i = 0; i < 4; i++) {
            int r = w * 16 + g + (i & 1) * 8;
            int c = kk * 16 + 2 * t + (i >> 1) * 8;
            float x = Ps[r * PP + c] * SCALE;
            float y = Ps[r * PP + c + 1] * SCALE;
            split_bf2(x, y, qh[kk][i], ql[kk][i]);
        }
    }
    __syncthreads();

    float mrow[2] = { -1e30f, -1e30f };   // rows g, g+8 (dup across quad)
    float lrow[2] = { 0.0f, 0.0f };
    float o[8][4] = {};

    const float* Bg = g_bias + ((size_t)b * SQ + q0) * SQ;
    const float* Kbase = g_K + (size_t)b * SQ * DD + h * HD;
    const float* Vbase = g_V + (size_t)b * SQ * DD + h * HD;

    for (int kt = 0; kt < SQ / 64; kt++) {
        const int k0 = kt * 64;
        const float* Kg = Kbase + (size_t)k0 * DD;
        const float* Vg = Vbase + (size_t)k0 * DD;

        __syncthreads();   // prior iteration's smem reads complete
        // Load + convert + store K (bf16 split) and V (tf32) tiles
        #pragma unroll
        for (int i = 0; i < 8; i++) {
            int e = tid + i * 256;      // word index 0..2047
            int r = e >> 5, c2 = e & 31;
            float2 v = *(const float2*)&Kg[(size_t)r * DD + 2 * c2];
            split_bf2(v.x, v.y, Khi[r * KP + c2], Klo[r * KP + c2]);
        }
        #pragma unroll
        for (int i = 0; i < 16; i++) {
            int e = tid + i * 256;      // 0..4095
            int r = e >> 6, c = e & 63;
            Vs[r * VP + c] = __uint_as_float(f2tf(Vg[(size_t)r * DD + c]));
        }
        __syncthreads();

        // ---- Issue bias loads early (hidden behind QK MMAs) ----
        float2 bq0[8], bq1[8];
        #pragma unroll
        for (int ns = 0; ns < 8; ns++) {
            int col = k0 + ns * 8 + 2 * t;
            bq0[ns] = *(const float2*)&Bg[(size_t)(w * 16 + g) * SQ + col];
            bq1[ns] = *(const float2*)&Bg[(size_t)(w * 16 + g + 8) * SQ + col];
        }

        // ---- S = Q @ K^T (bf16x3, m16n8k16) ----
        float s[8][4] = {};
        #pragma unroll
        for (int kk = 0; kk < 4; kk++) {
            #pragma unroll
            for (int ns = 0; ns < 8; ns++) {
                const int br = ns * 8 + g, bc = kk * 8 + t;
                uint32_t bh0 = Khi[br * KP + bc];
                uint32_t bh1 = Khi[br * KP + bc + 4];
                uint32_t bl0 = Klo[br * KP + bc];
                uint32_t bl1 = Klo[br * KP + bc + 4];
                mma_bf16(s[ns], qh[kk][0], qh[kk][1], qh[kk][2], qh[kk][3], bh0, bh1);
                mma_bf16(s[ns], qh[kk][0], qh[kk][1], qh[kk][2], qh[kk][3], bl0, bl1);
                mma_bf16(s[ns], ql[kk][0], ql[kk][1], ql[kk][2], ql[kk][3], bh0, bh1);
            }
        }

        // ---- Add combined bias ----
        #pragma unroll
        for (int ns = 0; ns < 8; ns++) {
            s[ns][0] += bq0[ns].x; s[ns][1] += bq0[ns].y;
            s[ns][2] += bq1[ns].x; s[ns][3] += bq1[ns].y;
        }

        // ---- Online softmax (registers + quad shfl) ----
        float tm0 = -1e30f, tm1 = -1e30f;
        #pragma unroll
        for (int ns = 0; ns < 8; ns++) {
            tm0 = fmaxf(tm0, fmaxf(s[ns][0], s[ns][1]));
            tm1 = fmaxf(tm1, fmaxf(s[ns][2], s[ns][3]));
        }
        tm0 = fmaxf(tm0, __shfl_xor_sync(0xffffffffu, tm0, 1));
        tm0 = fmaxf(tm0, __shfl_xor_sync(0xffffffffu, tm0, 2));
        tm1 = fmaxf(tm1, __shfl_xor_sync(0xffffffffu, tm1, 1));
        tm1 = fmaxf(tm1, __shfl_xor_sync(0xffffffffu, tm1, 2));

        float mn0 = fmaxf(mrow[0], tm0), mn1 = fmaxf(mrow[1], tm1);
        float cr0 = __expf(mrow[0] - mn0), cr1 = __expf(mrow[1] - mn1);
        float sum0 = 0.0f, sum1 = 0.0f;
        const int prow = w * 16 + g;
        #pragma unroll
        for (int ns = 0; ns < 8; ns++) {
            float p0 = __expf(s[ns][0] - mn0);
            float p1 = __expf(s[ns][1] - mn0);
            float p2 = __expf(s[ns][2] - mn1);
            float p3 = __expf(s[ns][3] - mn1);
            sum0 += p0 + p1; sum1 += p2 + p3;
            int pc = ns * 8 + 2 * t;
            Ps[prow * PP + pc]           = __uint_as_float(f2tf(p0));
            Ps[prow * PP + pc + 1]       = __uint_as_float(f2tf(p1));
            Ps[(prow + 8) * PP + pc]     = __uint_as_float(f2tf(p2));
            Ps[(prow + 8) * PP + pc + 1] = __uint_as_float(f2tf(p3));
            o[ns][0] *= cr0; o[ns][1] *= cr0;
            o[ns][2] *= cr1; o[ns][3] *= cr1;
        }
        sum0 += __shfl_xor_sync(0xffffffffu, sum0, 1);
        sum0 += __shfl_xor_sync(0xffffffffu, sum0, 2);
        sum1 += __shfl_xor_sync(0xffffffffu, sum1, 1);
        sum1 += __shfl_xor_sync(0xffffffffu, sum1, 2);
        lrow[0] = lrow[0] * cr0 + sum0;
        lrow[1] = lrow[1] * cr1 + sum1;
        mrow[0] = mn0; mrow[1] = mn1;
        __syncwarp();   // P rows are warp-private; cross-lane visibility only

        // ---- O += P @ V (tf32 single-pass) ----
        #pragma unroll
        for (int kk = 0; kk < 8; kk++) {
            uint32_t a0 = __float_as_uint(Ps[prow * PP + kk * 8 + t]);
            uint32_t a1 = __float_as_uint(Ps[(prow + 8) * PP + kk * 8 + t]);
            uint32_t a2 = __float_as_uint(Ps[prow * PP + kk * 8 + t + 4]);
            uint32_t a3 = __float_as_uint(Ps[(prow + 8) * PP + kk * 8 + t + 4]);
            #pragma unroll
            for (int ns = 0; ns < 8; ns++) {
                uint32_t b0 = __float_as_uint(Vs[(kk * 8 + t) * VP + ns * 8 + g]);
                uint32_t b1 = __float_as_uint(Vs[(kk * 8 + t + 4) * VP + ns * 8 + g]);
                mma_tf32(o[ns], a0, a1, a2, a3, b0, b1);
            }
        }
    }

    // ---- Normalize + write ctx ----
    float inv0 = 1.0f / lrow[0], inv1 = 1.0f / lrow[1];
    float* Cg = g_ctx + ((size_t)b * SQ + q0) * DD + h * HD;
    #pragma unroll
    for (int ns = 0; ns < 8; ns++) {
        int col = ns * 8 + 2 * t;
        float2 v0 = make_float2(o[ns][0] * inv0, o[ns][1] * inv0);
        float2 v1 = make_float2(o[ns][2] * inv1, o[ns][3] * inv1);
        *(float2*)&Cg[(size_t)(w * 16 + g) * DD + col] = v0;
        *(float2*)&Cg[(size_t)(w * 16 + g + 8) * DD + col] = v1;
    }
}

// ---------------------------------------------------------------------------
extern "C" void kernel_launch(void* const* d_in, const int* in_sizes, int n_in,
                              void* d_out, int out_size)
{
    const float* x     = (const float*)d_in[0];
    const float* Wq    = (const float*)d_in[1];
    const float* bq    = (const float*)d_in[2];
    const float* Wk    = (const float*)d_in[3];
    const float* bk    = (const float*)d_in[4];
    const float* Wv    = (const float*)d_in[5];
    const float* bv    = (const float*)d_in[6];
    const float* Wo    = (const float*)d_in[7];
    const float* bo    = (const float*)d_in[8];
    const float* amask = (const float*)d_in[9];
    const float* ipa   = (const float*)d_in[10];
    const float* assoc = (const float*)d_in[11];
    const int* cid            = (const int*)d_in[12];       // int32 (JAX x64 off)
    const unsigned char* kpm  = (const unsigned char*)d_in[13];
    float* out = (float*)d_out;

    cudaFuncSetAttribute(attn_tc_kernel, cudaFuncAttributeMaxDynamicSharedMemorySize, ATTN_SMEM);

    // QKV projections: bf16x3 tensor-core GEMM
    qkv_tc_kernel<<<dim3(DD / 64, (BB * SQ) / 128, 3), 256, GEMM_SMEM>>>(
        x, Wq, bq, Wk, bk, Wv, bv);

    // Combined bias matrix [B,S,S]
    bias_kernel<<<(BB * SQ * SQ) / 256, 256>>>(ipa, assoc, amask, cid, kpm);

    // Tensor-core flash attention (2 CTAs/SM)
    attn_tc_kernel<<<dim3(SQ / 128, NH, BB), 256, ATTN_SMEM>>>();

    // Output projection
    proj_tc_kernel<<<dim3(DD / 64, (BB * SQ) / 128), 256, GEMM_SMEM>>>(Wo, bo, out);
}

// round 8
// speedup vs baseline: 3.7880x; 1.0483x over previous
#include <cuda_runtime.h>
#include <math.h>
#include <stdint.h>

// Problem constants
#define BB 2
#define SQ 2048
#define DD 512
#define NH 8
#define HD 64
#define SCALE 0.125f   // 1/sqrt(64)
#define CBIAS 0.5f

// Scratch (device globals; no allocation allowed)
__device__ float    g_Q[BB * SQ * DD];
__device__ uint32_t g_Khw[BB * SQ * (DD / 2)];   // K as packed bf16x2 (hi)
__device__ uint32_t g_Klw[BB * SQ * (DD / 2)];   // K residual (lo)
__device__ float    g_Vt[BB * SQ * DD];          // V pre-rounded to tf32
__device__ float    g_ctx[BB * SQ * DD];
__device__ float    g_bias[(size_t)BB * SQ * SQ];

// ---------------------------------------------------------------------------
// Precision helpers
// ---------------------------------------------------------------------------
__device__ __forceinline__ uint32_t f2tf(float f) {
    uint32_t u;
    asm("cvt.rna.tf32.f32 %0, %1;" : "=r"(u) : "f"(f));
    return u;
}
__device__ __forceinline__ uint32_t pack_bf2(float e0, float e1) {
    uint32_t r;
    asm("cvt.rn.bf16x2.f32 %0, %1, %2;" : "=r"(r) : "f"(e1), "f"(e0));
    return r;
}
__device__ __forceinline__ float bf2_lo_f(uint32_t p) { return __uint_as_float(p << 16); }
__device__ __forceinline__ float bf2_hi_f(uint32_t p) { return __uint_as_float(p & 0xffff0000u); }
__device__ __forceinline__ void split_bf2(float x, float y, uint32_t& hi, uint32_t& lo) {
    hi = pack_bf2(x, y);
    lo = pack_bf2(x - bf2_lo_f(hi), y - bf2_hi_f(hi));
}

__device__ __forceinline__ void mma_bf16(float c[4],
    uint32_t a0, uint32_t a1, uint32_t a2, uint32_t a3,
    uint32_t b0, uint32_t b1)
{
    asm volatile(
        "mma.sync.aligned.m16n8k16.row.col.f32.bf16.bf16.f32 "
        "{%0,%1,%2,%3}, {%4,%5,%6,%7}, {%8,%9}, {%0,%1,%2,%3};"
        : "+f"(c[0]), "+f"(c[1]), "+f"(c[2]), "+f"(c[3])
        : "r"(a0), "r"(a1), "r"(a2), "r"(a3), "r"(b0), "r"(b1));
}
__device__ __forceinline__ void mma_tf32(float c[4],
    uint32_t a0, uint32_t a1, uint32_t a2, uint32_t a3,
    uint32_t b0, uint32_t b1)
{
    asm volatile(
        "mma.sync.aligned.m16n8k8.row.col.f32.tf32.tf32.f32 "
        "{%0,%1,%2,%3}, {%4,%5,%6,%7}, {%8,%9}, {%0,%1,%2,%3};"
        : "+f"(c[0]), "+f"(c[1]), "+f"(c[2]), "+f"(c[3])
        : "r"(a0), "r"(a1), "r"(a2), "r"(a3), "r"(b0), "r"(b1));
}

// cp.async helpers
__device__ __forceinline__ uint32_t smaddr(const void* p) {
    return (uint32_t)__cvta_generic_to_shared(p);
}
#define CP16(dst, src) asm volatile("cp.async.cg.shared.global [%0], [%1], 16;" :: "r"(dst), "l"(src))
#define CPCOMMIT()     asm volatile("cp.async.commit_group;")
#define CPWAIT(n)      asm volatile("cp.async.wait_group %0;" :: "n"(n))

// ---------------------------------------------------------------------------
// bf16x3 GEMM: C[M,N] = A[M,K] @ W[N,K]^T + bias[N]
// BM=128, BN=64, BK=32. 256 threads / 8 warps; warp = 16r x 64c.
// MODE epilogue: 0 = fp32 C, 1 = K split-bf16 words, 2 = V tf32 floats.
// ---------------------------------------------------------------------------
#define AP 20
#define GEMM_SMEM ((128 * AP * 2 + 64 * AP * 2) * 4)

template <int MODE>
__device__ __forceinline__ void gemm_tc_body(
    const float* __restrict__ A, const float* __restrict__ W,
    const float* __restrict__ bias, float* __restrict__ C,
    int m0, int n0)
{
    extern __shared__ uint32_t smu[];
    uint32_t* Ahi = smu;
    uint32_t* Alo = Ahi + 128 * AP;
    uint32_t* Whi = Alo + 128 * AP;
    uint32_t* Wlo = Whi + 64 * AP;

    const int tid = threadIdx.x;
    const int w = tid >> 5, lane = tid & 31;
    const int g = lane >> 2, t = lane & 3;

    float acc[8][4] = {};
    float2 pa[8], pw[4];

    #pragma unroll
    for (int i = 0; i < 8; i++) {
        int e = tid + i * 256;
        int r = e >> 4, c2 = e & 15;
        pa[i] = *(const float2*)&A[(size_t)(m0 + r) * DD + 2 * c2];
    }
    #pragma unroll
    for (int i = 0; i < 4; i++) {
        int e = tid + i * 256;
        int r = e >> 4, c2 = e & 15;
        pw[i] = *(const float2*)&W[(size_t)(n0 + r) * DD + 2 * c2];
    }

    for (int k0 = 0; k0 < DD; k0 += 32) {
        #pragma unroll
        for (int i = 0; i < 8; i++) {
            int e = tid + i * 256;
            int r = e >> 4, c2 = e & 15;
            split_bf2(pa[i].x, pa[i].y, Ahi[r * AP + c2], Alo[r * AP + c2]);
        }
        #pragma unroll
        for (int i = 0; i < 4; i++) {
            int e = tid + i * 256;
            int r = e >> 4, c2 = e & 15;
            split_bf2(pw[i].x, pw[i].y, Whi[r * AP + c2], Wlo[r * AP + c2]);
        }
        __syncthreads();

        if (k0 + 32 < DD) {
            #pragma unroll
            for (int i = 0; i < 8; i++) {
                int e = tid + i * 256;
                int r = e >> 4, c2 = e & 15;
                pa[i] = *(const float2*)&A[(size_t)(m0 + r) * DD + k0 + 32 + 2 * c2];
            }
            #pragma unroll
            for (int i = 0; i < 4; i++) {
                int e = tid + i * 256;
                int r = e >> 4, c2 = e & 15;
                pw[i] = *(const float2*)&W[(size_t)(n0 + r) * DD + k0 + 32 + 2 * c2];
            }
        }

        #pragma unroll
        for (int kk = 0; kk < 2; kk++) {
            const int ar = w * 16 + g, ac = kk * 8 + t;
            uint32_t ah0 = Ahi[ar * AP + ac];
            uint32_t ah1 = Ahi[(ar + 8) * AP + ac];
            uint32_t ah2 = Ahi[ar * AP + ac + 4];
            uint32_t ah3 = Ahi[(ar + 8) * AP + ac + 4];
            uint32_t al0 = Alo[ar * AP + ac];
            uint32_t al1 = Alo[(ar + 8) * AP + ac];
            uint32_t al2 = Alo[ar * AP + ac + 4];
            uint32_t al3 = Alo[(ar + 8) * AP + ac + 4];
            #pragma unroll
            for (int ns = 0; ns < 8; ns++) {
                const int br = ns * 8 + g, bc = kk * 8 + t;
                uint32_t bh0 = Whi[br * AP + bc];
                uint32_t bh1 = Whi[br * AP + bc + 4];
                uint32_t bl0 = Wlo[br * AP + bc];
                uint32_t bl1 = Wlo[br * AP + bc + 4];
                mma_bf16(acc[ns], ah0, ah1, ah2, ah3, bh0, bh1);
                mma_bf16(acc[ns], ah0, ah1, ah2, ah3, bl0, bl1);
                mma_bf16(acc[ns], al0, al1, al2, al3, bh0, bh1);
            }
        }
        __syncthreads();
    }

    // Epilogue
    #pragma unroll
    for (int ns = 0; ns < 8; ns++) {
        int n = n0 + ns * 8 + 2 * t;
        float b0 = bias[n], b1 = bias[n + 1];
        int r = m0 + w * 16 + g;
        float v00 = acc[ns][0] + b0, v01 = acc[ns][1] + b1;
        float v10 = acc[ns][2] + b0, v11 = acc[ns][3] + b1;
        if (MODE == 0) {
            *(float2*)&C[(size_t)r * DD + n] = make_float2(v00, v01);
            *(float2*)&C[(size_t)(r + 8) * DD + n] = make_float2(v10, v11);
        } else if (MODE == 1) {
            uint32_t hi0, lo0, hi1, lo1;
            split_bf2(v00, v01, hi0, lo0);
            split_bf2(v10, v11, hi1, lo1);
            size_t wcol = (size_t)(n >> 1);
            g_Khw[(size_t)r * (DD / 2) + wcol] = hi0;
            g_Klw[(size_t)r * (DD / 2) + wcol] = lo0;
            g_Khw[(size_t)(r + 8) * (DD / 2) + wcol] = hi1;
            g_Klw[(size_t)(r + 8) * (DD / 2) + wcol] = lo1;
        } else {
            *(float2*)&g_Vt[(size_t)r * DD + n] =
                make_float2(__uint_as_float(f2tf(v00)), __uint_as_float(f2tf(v01)));
            *(float2*)&g_Vt[(size_t)(r + 8) * DD + n] =
                make_float2(__uint_as_float(f2tf(v10)), __uint_as_float(f2tf(v11)));
        }
    }
}

__global__ __launch_bounds__(256) void qkv_tc_kernel(
    const float* __restrict__ x,
    const float* __restrict__ Wq, const float* __restrict__ bq,
    const float* __restrict__ Wk, const float* __restrict__ bk,
    const float* __restrict__ Wv, const float* __restrict__ bv)
{
    int m0 = blockIdx.y * 128, n0 = blockIdx.x * 64;
    if (blockIdx.z == 0)
        gemm_tc_body<0>(x, Wq, bq, g_Q, m0, n0);
    else if (blockIdx.z == 1)
        gemm_tc_body<1>(x, Wk, bk, nullptr, m0, n0);
    else
        gemm_tc_body<2>(x, Wv, bv, nullptr, m0, n0);
}

__global__ __launch_bounds__(256) void proj_tc_kernel(
    const float* __restrict__ Wo, const float* __restrict__ bo,
    float* __restrict__ out)
{
    gemm_tc_body<0>(g_ctx, Wo, bo, out, blockIdx.y * 128, blockIdx.x * 64);
}

// ---------------------------------------------------------------------------
// Combined additive bias
// ---------------------------------------------------------------------------
__global__ void bias_kernel(
    const float* __restrict__ ipa, const float* __restrict__ assoc,
    const float* __restrict__ amask,
    const int* __restrict__ cid, const unsigned char* __restrict__ kpm)
{
    int idx = blockIdx.x * 256 + threadIdx.x;
    int k = idx & (SQ - 1);
    int t = idx >> 11;
    int q = t & (SQ - 1);
    int b = t >> 11;

    int cq = cid[b * SQ + q];
    int ck = cid[b * SQ + k];
    float v = ipa[idx] + assoc[idx] + amask[q * SQ + k];
    if (cq == ck && cq >= 0 && ck >= 0 && q != k) v += CBIAS;
    if (kpm[b * SQ + k]) v = -1e30f;
    g_bias[idx] = v;
}

// ---------------------------------------------------------------------------
// Tensor-core flash attention with cp.async 2-stage K/V pipeline.
// K/V arrive pre-converted (split bf16 / tf32) from the QKV kernel.
// 2 CTAs/SM co-residency; 8 warps x 16 q-rows; QK bf16x3, PV tf32.
// ---------------------------------------------------------------------------
#define KP 36
#define VP 72
#define PP 68
#define KSTG (64 * KP)            // words per K stage (per hi/lo)
#define VSTG (64 * VP)            // floats per V stage
#define ATTN_SMEM ((2 * KSTG * 2 + 2 * VSTG + 128 * PP) * 4)
#define NKT (SQ / 64)

__global__ __launch_bounds__(256, 2) void attn_tc_kernel()
{
    extern __shared__ uint32_t smu[];
    uint32_t* KhiS = smu;                       // 2 stages
    uint32_t* KloS = KhiS + 2 * KSTG;
    float* VsS = (float*)(KloS + 2 * KSTG);     // 2 stages
    float* Ps  = VsS + 2 * VSTG;                // 128*PP

    const int tid = threadIdx.x;
    const int w = tid >> 5, lane = tid & 31;
    const int g = lane >> 2, t = lane & 3;
    const int q0 = blockIdx.x * 128;
    const int h  = blockIdx.y;
    const int b  = blockIdx.z;

    const uint32_t* KHsrc = g_Khw + (size_t)b * SQ * (DD / 2) + h * (HD / 2);
    const uint32_t* KLsrc = g_Klw + (size_t)b * SQ * (DD / 2) + h * (HD / 2);
    const float*    Vsrc  = g_Vt  + (size_t)b * SQ * DD + h * HD;

    // -- issue tile 0 loads immediately (overlap Q staging) --
    {
        #pragma unroll
        for (int i = 0; i < 2; i++) {
            int e = tid + i * 256;          // 0..511
            int r = e >> 3, c4 = (e & 7) * 4;
            CP16(smaddr(KhiS + r * KP + c4), KHsrc + (size_t)r * (DD / 2) + c4);
            CP16(smaddr(KloS + r * KP + c4), KLsrc + (size_t)r * (DD / 2) + c4);
        }
        #pragma unroll
        for (int i = 0; i < 4; i++) {
            int e = tid + i * 256;          // 0..1023
            int r = e >> 4, c4 = (e & 15) * 4;
            CP16(smaddr(VsS + r * VP + c4), Vsrc + (size_t)r * DD + c4);
        }
        CPCOMMIT();
    }

    // ---- Stage Q tile into Ps, build persistent bf16 A-fragments ----
    const float* Qg = g_Q + ((size_t)b * SQ + q0) * DD + h * HD;
    #pragma unroll
    for (int i = 0; i < 32; i++) {
        int e = tid + i * 256;
        int r = e >> 6, c = e & 63;
        Ps[r * PP + c] = Qg[(size_t)r * DD + c];
    }
    __syncthreads();

    uint32_t qh[4][4], ql[4][4];
    #pragma unroll
    for (int kk = 0; kk < 4; kk++) {
        #pragma unroll
        for (int i = 0; i < 4; i++) {
            int r = w * 16 + g + (i & 1) * 8;
            int c = kk * 16 + 2 * t + (i >> 1) * 8;
            float x = Ps[r * PP + c] * SCALE;
            float y = Ps[r * PP + c + 1] * SCALE;
            split_bf2(x, y, qh[kk][i], ql[kk][i]);
        }
    }
    __syncthreads();

    float mrow[2] = { -1e30f, -1e30f };
    float lrow[2] = { 0.0f, 0.0f };
    float o[8][4] = {};

    const float* Bg = g_bias + ((size_t)b * SQ + q0) * SQ;

    for (int kt = 0; kt < NKT; kt++) {
        // Issue next tile's loads (into the buffer freed last iteration)
        if (kt + 1 < NKT) {
            int s = (kt + 1) & 1;
            int k0n = (kt + 1) * 64;
            #pragma unroll
            for (int i = 0; i < 2; i++) {
                int e = tid + i * 256;
                int r = e >> 3, c4 = (e & 7) * 4;
                CP16(smaddr(KhiS + s * KSTG + r * KP + c4),
                     KHsrc + (size_t)(k0n + r) * (DD / 2) + c4);
                CP16(smaddr(KloS + s * KSTG + r * KP + c4),
                     KLsrc + (size_t)(k0n + r) * (DD / 2) + c4);
            }
            #pragma unroll
            for (int i = 0; i < 4; i++) {
                int e = tid + i * 256;
                int r = e >> 4, c4 = (e & 15) * 4;
                CP16(smaddr(VsS + s * VSTG + r * VP + c4),
                     Vsrc + (size_t)(k0n + r) * DD + c4);
            }
            CPCOMMIT();
            CPWAIT(1);
        } else {
            CPWAIT(0);
        }
        __syncthreads();

        const uint32_t* Khi = KhiS + (kt & 1) * KSTG;
        const uint32_t* Klo = KloS + (kt & 1) * KSTG;
        const float*    Vs  = VsS  + (kt & 1) * VSTG;
        const int k0 = kt * 64;

        // ---- Bias loads early (hidden behind QK MMAs) ----
        float2 bq0[8], bq1[8];
        #pragma unroll
        for (int ns = 0; ns < 8; ns++) {
            int col = k0 + ns * 8 + 2 * t;
            bq0[ns] = *(const float2*)&Bg[(size_t)(w * 16 + g) * SQ + col];
            bq1[ns] = *(const float2*)&Bg[(size_t)(w * 16 + g + 8) * SQ + col];
        }

        // ---- S = Q @ K^T (bf16x3) ----
        float s[8][4] = {};
        #pragma unroll
        for (int kk = 0; kk < 4; kk++) {
            #pragma unroll
            for (int ns = 0; ns < 8; ns++) {
                const int br = ns * 8 + g, bc = kk * 8 + t;
                uint32_t bh0 = Khi[br * KP + bc];
                uint32_t bh1 = Khi[br * KP + bc + 4];
                uint32_t bl0 = Klo[br * KP + bc];
                uint32_t bl1 = Klo[br * KP + bc + 4];
                mma_bf16(s[ns], qh[kk][0], qh[kk][1], qh[kk][2], qh[kk][3], bh0, bh1);
                mma_bf16(s[ns], qh[kk][0], qh[kk][1], qh[kk][2], qh[kk][3], bl0, bl1);
                mma_bf16(s[ns], ql[kk][0], ql[kk][1], ql[kk][2], ql[kk][3], bh0, bh1);
            }
        }

        #pragma unroll
        for (int ns = 0; ns < 8; ns++) {
            s[ns][0] += bq0[ns].x; s[ns][1] += bq0[ns].y;
            s[ns][2] += bq1[ns].x; s[ns][3] += bq1[ns].y;
        }

        // ---- Online softmax (registers + quad shfl) ----
        float tm0 = -1e30f, tm1 = -1e30f;
        #pragma unroll
        for (int ns = 0; ns < 8; ns++) {
            tm0 = fmaxf(tm0, fmaxf(s[ns][0], s[ns][1]));
            tm1 = fmaxf(tm1, fmaxf(s[ns][2], s[ns][3]));
        }
        tm0 = fmaxf(tm0, __shfl_xor_sync(0xffffffffu, tm0, 1));
        tm0 = fmaxf(tm0, __shfl_xor_sync(0xffffffffu, tm0, 2));
        tm1 = fmaxf(tm1, __shfl_xor_sync(0xffffffffu, tm1, 1));
        tm1 = fmaxf(tm1, __shfl_xor_sync(0xffffffffu, tm1, 2));

        float mn0 = fmaxf(mrow[0], tm0), mn1 = fmaxf(mrow[1], tm1);
        float cr0 = __expf(mrow[0] - mn0), cr1 = __expf(mrow[1] - mn1);
        float sum0 = 0.0f, sum1 = 0.0f;
        const int prow = w * 16 + g;
        #pragma unroll
        for (int ns = 0; ns < 8; ns++) {
            float p0 = __expf(s[ns][0] - mn0);
            float p1 = __expf(s[ns][1] - mn0);
            float p2 = __expf(s[ns][2] - mn1);
            float p3 = __expf(s[ns][3] - mn1);
            sum0 += p0 + p1; sum1 += p2 + p3;
            int pc = ns * 8 + 2 * t;
            Ps[prow * PP + pc]           = __uint_as_float(f2tf(p0));
            Ps[prow * PP + pc + 1]       = __uint_as_float(f2tf(p1));
            Ps[(prow + 8) * PP + pc]     = __uint_as_float(f2tf(p2));
            Ps[(prow + 8) * PP + pc + 1] = __uint_as_float(f2tf(p3));
            o[ns][0] *= cr0; o[ns][1] *= cr0;
            o[ns][2] *= cr1; o[ns][3] *= cr1;
        }
        sum0 += __shfl_xor_sync(0xffffffffu, sum0, 1);
        sum0 += __shfl_xor_sync(0xffffffffu, sum0, 2);
        sum1 += __shfl_xor_sync(0xffffffffu, sum1, 1);
        sum1 += __shfl_xor_sync(0xffffffffu, sum1, 2);
        lrow[0] = lrow[0] * cr0 + sum0;
        lrow[1] = lrow[1] * cr1 + sum1;
        mrow[0] = mn0; mrow[1] = mn1;
        __syncwarp();   // P rows are warp-private

        // ---- O += P @ V (tf32 single-pass) ----
        #pragma unroll
        for (int kk = 0; kk < 8; kk++) {
            uint32_t a0 = __float_as_uint(Ps[prow * PP + kk * 8 + t]);
            uint32_t a1 = __float_as_uint(Ps[(prow + 8) * PP + kk * 8 + t]);
            uint32_t a2 = __float_as_uint(Ps[prow * PP + kk * 8 + t + 4]);
            uint32_t a3 = __float_as_uint(Ps[(prow + 8) * PP + kk * 8 + t + 4]);
            #pragma unroll
            for (int ns = 0; ns < 8; ns++) {
                uint32_t b0 = __float_as_uint(Vs[(kk * 8 + t) * VP + ns * 8 + g]);
                uint32_t b1 = __float_as_uint(Vs[(kk * 8 + t + 4) * VP + ns * 8 + g]);
                mma_tf32(o[ns], a0, a1, a2, a3, b0, b1);
            }
        }
        __syncthreads();   // protect stage buffer before next issue
    }

    // ---- Normalize + write ctx ----
    float inv0 = 1.0f / lrow[0], inv1 = 1.0f / lrow[1];
    float* Cg = g_ctx + ((size_t)b * SQ + q0) * DD + h * HD;
    #pragma unroll
    for (int ns = 0; ns < 8; ns++) {
        int col = ns * 8 + 2 * t;
        float2 v0 = make_float2(o[ns][0] * inv0, o[ns][1] * inv0);
        float2 v1 = make_float2(o[ns][2] * inv1, o[ns][3] * inv1);
        *(float2*)&Cg[(size_t)(w * 16 + g) * DD + col] = v0;
        *(float2*)&Cg[(size_t)(w * 16 + g + 8) * DD + col] = v1;
    }
}

// ---------------------------------------------------------------------------
extern "C" void kernel_launch(void* const* d_in, const int* in_sizes, int n_in,
                              void* d_out, int out_size)
{
    const float* x     = (const float*)d_in[0];
    const float* Wq    = (const float*)d_in[1];
    const float* bq    = (const float*)d_in[2];
    const float* Wk    = (const float*)d_in[3];
    const float* bk    = (const float*)d_in[4];
    const float* Wv    = (const float*)d_in[5];
    const float* bv    = (const float*)d_in[6];
    const float* Wo    = (const float*)d_in[7];
    const float* bo    = (const float*)d_in[8];
    const float* amask = (const float*)d_in[9];
    const float* ipa   = (const float*)d_in[10];
    const float* assoc = (const float*)d_in[11];
    const int* cid            = (const int*)d_in[12];       // int32 (JAX x64 off)
    const unsigned char* kpm  = (const unsigned char*)d_in[13];
    float* out = (float*)d_out;

    cudaFuncSetAttribute(attn_tc_kernel, cudaFuncAttributeMaxDynamicSharedMemorySize, ATTN_SMEM);

    // QKV projections (K written pre-split bf16, V pre-rounded tf32)
    qkv_tc_kernel<<<dim3(DD / 64, (BB * SQ) / 128, 3), 256, GEMM_SMEM>>>(
        x, Wq, bq, Wk, bk, Wv, bv);

    // Combined bias matrix [B,S,S]
    bias_kernel<<<(BB * SQ * SQ) / 256, 256>>>(ipa, assoc, amask, cid, kpm);

    // Tensor-core flash attention (2 CTAs/SM, cp.async pipelined)
    attn_tc_kernel<<<dim3(SQ / 128, NH, BB), 256, ATTN_SMEM>>>();

    // Output projection
    proj_tc_kernel<<<dim3(DD / 64, (BB * SQ) / 128), 256, GEMM_SMEM>>>(Wo, bo, out);
}

// round 9
// speedup vs baseline: 3.9462x; 1.0418x over previous
#include <cuda_runtime.h>
#include <math.h>
#include <stdint.h>

// Problem constants
#define BB 2
#define SQ 2048
#define DD 512
#define NH 8
#define HD 64
#define SCALE 0.125f   // 1/sqrt(64)
#define CBIAS 0.5f
#define LOG2E 1.4426950408889634f
#define SCALE_L2E (SCALE * LOG2E)

// Scratch (device globals; no allocation allowed)
__device__ float    g_Q[BB * SQ * DD];
__device__ uint32_t g_Khw[BB * SQ * (DD / 2)];   // K as packed bf16x2 (hi)
__device__ uint32_t g_Klw[BB * SQ * (DD / 2)];   // K residual (lo)
__device__ float    g_Vt[BB * SQ * DD];          // V pre-rounded to tf32
__device__ float    g_ctx[BB * SQ * DD];
__device__ float    g_bias[(size_t)BB * SQ * SQ]; // combined bias * log2(e)

// ---------------------------------------------------------------------------
// Precision helpers
// ---------------------------------------------------------------------------
__device__ __forceinline__ uint32_t f2tf(float f) {
    uint32_t u;
    asm("cvt.rna.tf32.f32 %0, %1;" : "=r"(u) : "f"(f));
    return u;
}
__device__ __forceinline__ uint32_t pack_bf2(float e0, float e1) {
    uint32_t r;
    asm("cvt.rn.bf16x2.f32 %0, %1, %2;" : "=r"(r) : "f"(e1), "f"(e0));
    return r;
}
__device__ __forceinline__ float bf2_lo_f(uint32_t p) { return __uint_as_float(p << 16); }
__device__ __forceinline__ float bf2_hi_f(uint32_t p) { return __uint_as_float(p & 0xffff0000u); }
__device__ __forceinline__ void split_bf2(float x, float y, uint32_t& hi, uint32_t& lo) {
    hi = pack_bf2(x, y);
    lo = pack_bf2(x - bf2_lo_f(hi), y - bf2_hi_f(hi));
}

__device__ __forceinline__ void mma_bf16(float c[4],
    uint32_t a0, uint32_t a1, uint32_t a2, uint32_t a3,
    uint32_t b0, uint32_t b1)
{
    asm volatile(
        "mma.sync.aligned.m16n8k16.row.col.f32.bf16.bf16.f32 "
        "{%0,%1,%2,%3}, {%4,%5,%6,%7}, {%8,%9}, {%0,%1,%2,%3};"
        : "+f"(c[0]), "+f"(c[1]), "+f"(c[2]), "+f"(c[3])
        : "r"(a0), "r"(a1), "r"(a2), "r"(a3), "r"(b0), "r"(b1));
}
__device__ __forceinline__ void mma_tf32(float c[4],
    uint32_t a0, uint32_t a1, uint32_t a2, uint32_t a3,
    uint32_t b0, uint32_t b1)
{
    asm volatile(
        "mma.sync.aligned.m16n8k8.row.col.f32.tf32.tf32.f32 "
        "{%0,%1,%2,%3}, {%4,%5,%6,%7}, {%8,%9}, {%0,%1,%2,%3};"
        : "+f"(c[0]), "+f"(c[1]), "+f"(c[2]), "+f"(c[3])
        : "r"(a0), "r"(a1), "r"(a2), "r"(a3), "r"(b0), "r"(b1));
}

// cp.async helpers
__device__ __forceinline__ uint32_t smaddr(const void* p) {
    return (uint32_t)__cvta_generic_to_shared(p);
}
#define CP16(dst, src) asm volatile("cp.async.cg.shared.global [%0], [%1], 16;" :: "r"(dst), "l"(src))
#define CPCOMMIT()     asm volatile("cp.async.commit_group;")
#define CPWAIT(n)      asm volatile("cp.async.wait_group %0;" :: "n"(n))

// ---------------------------------------------------------------------------
// bf16x3 GEMM: C[M,N] = A[M,K] @ W[N,K]^T + bias[N]
// BM=128, BN=64, BK=32. 256 threads / 8 warps; warp = 16r x 64c.
// MODE epilogue: 0 = fp32 C, 1 = K split-bf16 words, 2 = V tf32 floats.
// ---------------------------------------------------------------------------
#define AP 20
#define GEMM_SMEM ((128 * AP * 2 + 64 * AP * 2) * 4)

template <int MODE>
__device__ __forceinline__ void gemm_tc_body(
    const float* __restrict__ A, const float* __restrict__ W,
    const float* __restrict__ bias, float* __restrict__ C,
    int m0, int n0)
{
    extern __shared__ uint32_t smu[];
    uint32_t* Ahi = smu;
    uint32_t* Alo = Ahi + 128 * AP;
    uint32_t* Whi = Alo + 128 * AP;
    uint32_t* Wlo = Whi + 64 * AP;

    const int tid = threadIdx.x;
    const int w = tid >> 5, lane = tid & 31;
    const int g = lane >> 2, t = lane & 3;

    float acc[8][4] = {};
    float2 pa[8], pw[4];

    #pragma unroll
    for (int i = 0; i < 8; i++) {
        int e = tid + i * 256;
        int r = e >> 4, c2 = e & 15;
        pa[i] = *(const float2*)&A[(size_t)(m0 + r) * DD + 2 * c2];
    }
    #pragma unroll
    for (int i = 0; i < 4; i++) {
        int e = tid + i * 256;
        int r = e >> 4, c2 = e & 15;
        pw[i] = *(const float2*)&W[(size_t)(n0 + r) * DD + 2 * c2];
    }

    for (int k0 = 0; k0 < DD; k0 += 32) {
        #pragma unroll
        for (int i = 0; i < 8; i++) {
            int e = tid + i * 256;
            int r = e >> 4, c2 = e & 15;
            split_bf2(pa[i].x, pa[i].y, Ahi[r * AP + c2], Alo[r * AP + c2]);
        }
        #pragma unroll
        for (int i = 0; i < 4; i++) {
            int e = tid + i * 256;
            int r = e >> 4, c2 = e & 15;
            split_bf2(pw[i].x, pw[i].y, Whi[r * AP + c2], Wlo[r * AP + c2]);
        }
        __syncthreads();

        if (k0 + 32 < DD) {
            #pragma unroll
            for (int i = 0; i < 8; i++) {
                int e = tid + i * 256;
                int r = e >> 4, c2 = e & 15;
                pa[i] = *(const float2*)&A[(size_t)(m0 + r) * DD + k0 + 32 + 2 * c2];
            }
            #pragma unroll
            for (int i = 0; i < 4; i++) {
                int e = tid + i * 256;
                int r = e >> 4, c2 = e & 15;
                pw[i] = *(const float2*)&W[(size_t)(n0 + r) * DD + k0 + 32 + 2 * c2];
            }
        }

        #pragma unroll
        for (int kk = 0; kk < 2; kk++) {
            const int ar = w * 16 + g, ac = kk * 8 + t;
            uint32_t ah0 = Ahi[ar * AP + ac];
            uint32_t ah1 = Ahi[(ar + 8) * AP + ac];
            uint32_t ah2 = Ahi[ar * AP + ac + 4];
            uint32_t ah3 = Ahi[(ar + 8) * AP + ac + 4];
            uint32_t al0 = Alo[ar * AP + ac];
            uint32_t al1 = Alo[(ar + 8) * AP + ac];
            uint32_t al2 = Alo[ar * AP + ac + 4];
            uint32_t al3 = Alo[(ar + 8) * AP + ac + 4];
            #pragma unroll
            for (int ns = 0; ns < 8; ns++) {
                const int br = ns * 8 + g, bc = kk * 8 + t;
                uint32_t bh0 = Whi[br * AP + bc];
                uint32_t bh1 = Whi[br * AP + bc + 4];
                uint32_t bl0 = Wlo[br * AP + bc];
                uint32_t bl1 = Wlo[br * AP + bc + 4];
                mma_bf16(acc[ns], ah0, ah1, ah2, ah3, bh0, bh1);
                mma_bf16(acc[ns], ah0, ah1, ah2, ah3, bl0, bl1);
                mma_bf16(acc[ns], al0, al1, al2, al3, bh0, bh1);
            }
        }
        __syncthreads();
    }

    // Epilogue
    #pragma unroll
    for (int ns = 0; ns < 8; ns++) {
        int n = n0 + ns * 8 + 2 * t;
        float b0 = bias[n], b1 = bias[n + 1];
        int r = m0 + w * 16 + g;
        float v00 = acc[ns][0] + b0, v01 = acc[ns][1] + b1;
        float v10 = acc[ns][2] + b0, v11 = acc[ns][3] + b1;
        if (MODE == 0) {
            *(float2*)&C[(size_t)r * DD + n] = make_float2(v00, v01);
            *(float2*)&C[(size_t)(r + 8) * DD + n] = make_float2(v10, v11);
        } else if (MODE == 1) {
            uint32_t hi0, lo0, hi1, lo1;
            split_bf2(v00, v01, hi0, lo0);
            split_bf2(v10, v11, hi1, lo1);
            size_t wcol = (size_t)(n >> 1);
            g_Khw[(size_t)r * (DD / 2) + wcol] = hi0;
            g_Klw[(size_t)r * (DD / 2) + wcol] = lo0;
            g_Khw[(size_t)(r + 8) * (DD / 2) + wcol] = hi1;
            g_Klw[(size_t)(r + 8) * (DD / 2) + wcol] = lo1;
        } else {
            *(float2*)&g_Vt[(size_t)r * DD + n] =
                make_float2(__uint_as_float(f2tf(v00)), __uint_as_float(f2tf(v01)));
            *(float2*)&g_Vt[(size_t)(r + 8) * DD + n] =
                make_float2(__uint_as_float(f2tf(v10)), __uint_as_float(f2tf(v11)));
        }
    }
}

// ---------------------------------------------------------------------------
// Fused QKV + bias kernel. z in {0,1,2}: GEMM planes. z == 3: combined bias
// (memory-bound, overlaps the tensor-bound GEMM planes on the same SMs).
// Bias is stored pre-multiplied by log2(e) for exp2-based softmax.
// ---------------------------------------------------------------------------
__global__ __launch_bounds__(256) void qkv_bias_kernel(
    const float* __restrict__ x,
    const float* __restrict__ Wq, const float* __restrict__ bq,
    const float* __restrict__ Wk, const float* __restrict__ bk,
    const float* __restrict__ Wv, const float* __restrict__ bv,
    const float* __restrict__ ipa, const float* __restrict__ assoc,
    const float* __restrict__ amask,
    const int* __restrict__ cid, const unsigned char* __restrict__ kpm)
{
    int m0 = blockIdx.y * 128, n0 = blockIdx.x * 64;
    if (blockIdx.z == 0) {
        gemm_tc_body<0>(x, Wq, bq, g_Q, m0, n0);
    } else if (blockIdx.z == 1) {
        gemm_tc_body<1>(x, Wk, bk, nullptr, m0, n0);
    } else if (blockIdx.z == 2) {
        gemm_tc_body<2>(x, Wv, bv, nullptr, m0, n0);
    } else {
        // Bias plane: grid-stride float4 over BB*SQ*SQ elements
        const int nthreads = gridDim.x * gridDim.y * 256;   // 65536
        const int tglob = (blockIdx.y * gridDim.x + blockIdx.x) * 256 + threadIdx.x;
        const int npacks = (BB * SQ * SQ) / 4;              // 2097152
        for (int p = tglob; p < npacks; p += nthreads) {
            int idx = p * 4;
            int k4 = idx & (SQ - 1);
            int t2 = idx >> 11;
            int q = t2 & (SQ - 1);
            int b = t2 >> 11;

            float4 vi = *(const float4*)&ipa[idx];
            float4 va = *(const float4*)&assoc[idx];
            float4 vm = *(const float4*)&amask[q * SQ + k4];
            int4 ck4 = *(const int4*)&cid[b * SQ + k4];
            uchar4 kp4 = *(const uchar4*)&kpm[b * SQ + k4];
            int cq = cid[b * SQ + q];
            bool qv = cq >= 0;

            float r0 = vi.x + va.x + vm.x;
            float r1 = vi.y + va.y + vm.y;
            float r2 = vi.z + va.z + vm.z;
            float r3 = vi.w + va.w + vm.w;
            if (qv && cq == ck4.x && q != k4)     r0 += CBIAS;
            if (qv && cq == ck4.y && q != k4 + 1) r1 += CBIAS;
            if (qv && cq == ck4.z && q != k4 + 2) r2 += CBIAS;
            if (qv && cq == ck4.w && q != k4 + 3) r3 += CBIAS;
            if (kp4.x) r0 = -1e30f;
            if (kp4.y) r1 = -1e30f;
            if (kp4.z) r2 = -1e30f;
            if (kp4.w) r3 = -1e30f;
            *(float4*)&g_bias[idx] = make_float4(r0 * LOG2E, r1 * LOG2E,
                                                 r2 * LOG2E, r3 * LOG2E);
        }
    }
}

__global__ __launch_bounds__(256) void proj_tc_kernel(
    const float* __restrict__ Wo, const float* __restrict__ bo,
    float* __restrict__ out)
{
    gemm_tc_body<0>(g_ctx, Wo, bo, out, blockIdx.y * 128, blockIdx.x * 64);
}

// ---------------------------------------------------------------------------
// Tensor-core flash attention with cp.async 2-stage K/V pipeline.
// exp2-based softmax (bias & Q pre-scaled by log2 e). P fed to tf32 MMA
// without explicit rounding (HW truncates; P in [0,1]).
// ---------------------------------------------------------------------------
#define KP 36
#define VP 72
#define PP 68
#define KSTG (64 * KP)
#define VSTG (64 * VP)
#define ATTN_SMEM ((2 * KSTG * 2 + 2 * VSTG + 128 * PP) * 4)
#define NKT (SQ / 64)

__global__ __launch_bounds__(256, 2) void attn_tc_kernel()
{
    extern __shared__ uint32_t smu[];
    uint32_t* KhiS = smu;                       // 2 stages
    uint32_t* KloS = KhiS + 2 * KSTG;
    float* VsS = (float*)(KloS + 2 * KSTG);     // 2 stages
    float* Ps  = VsS + 2 * VSTG;                // 128*PP

    const int tid = threadIdx.x;
    const int w = tid >> 5, lane = tid & 31;
    const int g = lane >> 2, t = lane & 3;
    const int q0 = blockIdx.x * 128;
    const int h  = blockIdx.y;
    const int b  = blockIdx.z;

    const uint32_t* KHsrc = g_Khw + (size_t)b * SQ * (DD / 2) + h * (HD / 2);
    const uint32_t* KLsrc = g_Klw + (size_t)b * SQ * (DD / 2) + h * (HD / 2);
    const float*    Vsrc  = g_Vt  + (size_t)b * SQ * DD + h * HD;

    // -- issue tile 0 loads immediately (overlap Q staging) --
    {
        #pragma unroll
        for (int i = 0; i < 2; i++) {
            int e = tid + i * 256;
            int r = e >> 3, c4 = (e & 7) * 4;
            CP16(smaddr(KhiS + r * KP + c4), KHsrc + (size_t)r * (DD / 2) + c4);
            CP16(smaddr(KloS + r * KP + c4), KLsrc + (size_t)r * (DD / 2) + c4);
        }
        #pragma unroll
        for (int i = 0; i < 4; i++) {
            int e = tid + i * 256;
            int r = e >> 4, c4 = (e & 15) * 4;
            CP16(smaddr(VsS + r * VP + c4), Vsrc + (size_t)r * DD + c4);
        }
        CPCOMMIT();
    }

    // ---- Stage Q tile into Ps, build persistent bf16 A-fragments ----
    const float* Qg = g_Q + ((size_t)b * SQ + q0) * DD + h * HD;
    #pragma unroll
    for (int i = 0; i < 32; i++) {
        int e = tid + i * 256;
        int r = e >> 6, c = e & 63;
        Ps[r * PP + c] = Qg[(size_t)r * DD + c];
    }
    __syncthreads();

    uint32_t qh[4][4], ql[4][4];
    #pragma unroll
    for (int kk = 0; kk < 4; kk++) {
        #pragma unroll
        for (int i = 0; i < 4; i++) {
            int r = w * 16 + g + (i & 1) * 8;
            int c = kk * 16 + 2 * t + (i >> 1) * 8;
            float x = Ps[r * PP + c] * SCALE_L2E;
            float y = Ps[r * PP + c + 1] * SCALE_L2E;
            split_bf2(x, y, qh[kk][i], ql[kk][i]);
        }
    }
    __syncthreads();

    float mrow[2] = { -1e30f, -1e30f };
    float lrow[2] = { 0.0f, 0.0f };
    float o[8][4] = {};

    const float* Bg = g_bias + ((size_t)b * SQ + q0) * SQ;

    for (int kt = 0; kt < NKT; kt++) {
        if (kt + 1 < NKT) {
            int s = (kt + 1) & 1;
            int k0n = (kt + 1) * 64;
            #pragma unroll
            for (int i = 0; i < 2; i++) {
                int e = tid + i * 256;
                int r = e >> 3, c4 = (e & 7) * 4;
                CP16(smaddr(KhiS + s * KSTG + r * KP + c4),
                     KHsrc + (size_t)(k0n + r) * (DD / 2) + c4);
                CP16(smaddr(KloS + s * KSTG + r * KP + c4),
                     KLsrc + (size_t)(k0n + r) * (DD / 2) + c4);
            }
            #pragma unroll
            for (int i = 0; i < 4; i++) {
                int e = tid + i * 256;
                int r = e >> 4, c4 = (e & 15) * 4;
                CP16(smaddr(VsS + s * VSTG + r * VP + c4),
                     Vsrc + (size_t)(k0n + r) * DD + c4);
            }
            CPCOMMIT();
            CPWAIT(1);
        } else {
            CPWAIT(0);
        }
        __syncthreads();

        const uint32_t* Khi = KhiS + (kt & 1) * KSTG;
        const uint32_t* Klo = KloS + (kt & 1) * KSTG;
        const float*    Vs  = VsS  + (kt & 1) * VSTG;
        const int k0 = kt * 64;

        // ---- Bias loads early (hidden behind QK MMAs) ----
        float2 bq0[8], bq1[8];
        #pragma unroll
        for (int ns = 0; ns < 8; ns++) {
            int col = k0 + ns * 8 + 2 * t;
            bq0[ns] = *(const float2*)&Bg[(size_t)(w * 16 + g) * SQ + col];
            bq1[ns] = *(const float2*)&Bg[(size_t)(w * 16 + g + 8) * SQ + col];
        }

        // ---- S = Q @ K^T (bf16x3) ----
        float s[8][4] = {};
        #pragma unroll
        for (int kk = 0; kk < 4; kk++) {
            #pragma unroll
            for (int ns = 0; ns < 8; ns++) {
                const int br = ns * 8 + g, bc = kk * 8 + t;
                uint32_t bh0 = Khi[br * KP + bc];
                uint32_t bh1 = Khi[br * KP + bc + 4];
                uint32_t bl0 = Klo[br * KP + bc];
                uint32_t bl1 = Klo[br * KP + bc + 4];
                mma_bf16(s[ns], qh[kk][0], qh[kk][1], qh[kk][2], qh[kk][3], bh0, bh1);
                mma_bf16(s[ns], qh[kk][0], qh[kk][1], qh[kk][2], qh[kk][3], bl0, bl1);
                mma_bf16(s[ns], ql[kk][0], ql[kk][1], ql[kk][2], ql[kk][3], bh0, bh1);
            }
        }

        #pragma unroll
        for (int ns = 0; ns < 8; ns++) {
            s[ns][0] += bq0[ns].x; s[ns][1] += bq0[ns].y;
            s[ns][2] += bq1[ns].x; s[ns][3] += bq1[ns].y;
        }

        // ---- Online softmax (exp2, registers + quad shfl) ----
        float tm0 = -1e30f, tm1 = -1e30f;
        #pragma unroll
        for (int ns = 0; ns < 8; ns++) {
            tm0 = fmaxf(tm0, fmaxf(s[ns][0], s[ns][1]));
            tm1 = fmaxf(tm1, fmaxf(s[ns][2], s[ns][3]));
        }
        tm0 = fmaxf(tm0, __shfl_xor_sync(0xffffffffu, tm0, 1));
        tm0 = fmaxf(tm0, __shfl_xor_sync(0xffffffffu, tm0, 2));
        tm1 = fmaxf(tm1, __shfl_xor_sync(0xffffffffu, tm1, 1));
        tm1 = fmaxf(tm1, __shfl_xor_sync(0xffffffffu, tm1, 2));

        float mn0 = fmaxf(mrow[0], tm0), mn1 = fmaxf(mrow[1], tm1);
        float cr0 = exp2f(mrow[0] - mn0), cr1 = exp2f(mrow[1] - mn1);
        float sum0 = 0.0f, sum1 = 0.0f;
        const int prow = w * 16 + g;
        #pragma unroll
        for (int ns = 0; ns < 8; ns++) {
            float p0 = exp2f(s[ns][0] - mn0);
            float p1 = exp2f(s[ns][1] - mn0);
            float p2 = exp2f(s[ns][2] - mn1);
            float p3 = exp2f(s[ns][3] - mn1);
            sum0 += p0 + p1; sum1 += p2 + p3;
            int pc = ns * 8 + 2 * t;
            Ps[prow * PP + pc]           = p0;   // raw fp32; tf32 MMA truncates
            Ps[prow * PP + pc + 1]       = p1;
            Ps[(prow + 8) * PP + pc]     = p2;
            Ps[(prow + 8) * PP + pc + 1] = p3;
            o[ns][0] *= cr0; o[ns][1] *= cr0;
            o[ns][2] *= cr1; o[ns][3] *= cr1;
        }
        sum0 += __shfl_xor_sync(0xffffffffu, sum0, 1);
        sum0 += __shfl_xor_sync(0xffffffffu, sum0, 2);
        sum1 += __shfl_xor_sync(0xffffffffu, sum1, 1);
        sum1 += __shfl_xor_sync(0xffffffffu, sum1, 2);
        lrow[0] = lrow[0] * cr0 + sum0;
        lrow[1] = lrow[1] * cr1 + sum1;
        mrow[0] = mn0; mrow[1] = mn1;
        __syncwarp();

        // ---- O += P @ V (tf32 single-pass) ----
        #pragma unroll
        for (int kk = 0; kk < 8; kk++) {
            uint32_t a0 = __float_as_uint(Ps[prow * PP + kk * 8 + t]);
            uint32_t a1 = __float_as_uint(Ps[(prow + 8) * PP + kk * 8 + t]);
            uint32_t a2 = __float_as_uint(Ps[prow * PP + kk * 8 + t + 4]);
            uint32_t a3 = __float_as_uint(Ps[(prow + 8) * PP + kk * 8 + t + 4]);
            #pragma unroll
            for (int ns = 0; ns < 8; ns++) {
                uint32_t b0 = __float_as_uint(Vs[(kk * 8 + t) * VP + ns * 8 + g]);
                uint32_t b1 = __float_as_uint(Vs[(kk * 8 + t + 4) * VP + ns * 8 + g]);
                mma_tf32(o[ns], a0, a1, a2, a3, b0, b1);
            }
        }
        __syncthreads();
    }

    // ---- Normalize + write ctx ----
    float inv0 = 1.0f / lrow[0], inv1 = 1.0f / lrow[1];
    float* Cg = g_ctx + ((size_t)b * SQ + q0) * DD + h * HD;
    #pragma unroll
    for (int ns = 0; ns < 8; ns++) {
        int col = ns * 8 + 2 * t;
        float2 v0 = make_float2(o[ns][0] * inv0, o[ns][1] * inv0);
        float2 v1 = make_float2(o[ns][2] * inv1, o[ns][3] * inv1);
        *(float2*)&Cg[(size_t)(w * 16 + g) * DD + col] = v0;
        *(float2*)&Cg[(size_t)(w * 16 + g + 8) * DD + col] = v1;
    }
}

// ---------------------------------------------------------------------------
extern "C" void kernel_launch(void* const* d_in, const int* in_sizes, int n_in,
                              void* d_out, int out_size)
{
    const float* x     = (const float*)d_in[0];
    const float* Wq    = (const float*)d_in[1];
    const float* bq    = (const float*)d_in[2];
    const float* Wk    = (const float*)d_in[3];
    const float* bk    = (const float*)d_in[4];
    const float* Wv    = (const float*)d_in[5];
    const float* bv    = (const float*)d_in[6];
    const float* Wo    = (const float*)d_in[7];
    const float* bo    = (const float*)d_in[8];
    const float* amask = (const float*)d_in[9];
    const float* ipa   = (const float*)d_in[10];
    const float* assoc = (const float*)d_in[11];
    const int* cid            = (const int*)d_in[12];       // int32 (JAX x64 off)
    const unsigned char* kpm  = (const unsigned char*)d_in[13];
    float* out = (float*)d_out;

    cudaFuncSetAttribute(attn_tc_kernel, cudaFuncAttributeMaxDynamicSharedMemorySize, ATTN_SMEM);

    // Fused QKV projections + combined bias (z = 3 plane)
    qkv_bias_kernel<<<dim3(DD / 64, (BB * SQ) / 128, 4), 256, GEMM_SMEM>>>(
        x, Wq, bq, Wk, bk, Wv, bv, ipa, assoc, amask, cid, kpm);

    // Tensor-core flash attention (2 CTAs/SM, cp.async pipelined)
    attn_tc_kernel<<<dim3(SQ / 128, NH, BB), 256, ATTN_SMEM>>>();

    // Output projection
    proj_tc_kernel<<<dim3(DD / 64, (BB * SQ) / 128), 256, GEMM_SMEM>>>(Wo, bo, out);
}

// round 10
// speedup vs baseline: 4.0420x; 1.0243x over previous
#include <cuda_runtime.h>
#include <math.h>
#include <stdint.h>

// Problem constants
#define BB 2
#define SQ 2048
#define DD 512
#define NH 8
#define HD 64
#define SCALE 0.125f   // 1/sqrt(64)
#define CBIAS 0.5f
#define LOG2E 1.4426950408889634f
#define SCALE_L2E (SCALE * LOG2E)

// Scratch (device globals; no allocation allowed)
__device__ float    g_Q[BB * SQ * DD];
__device__ uint32_t g_Khw[BB * SQ * (DD / 2)];   // K as packed bf16x2 (hi)
__device__ uint32_t g_Klw[BB * SQ * (DD / 2)];   // K residual (lo)
__device__ float    g_Vt[BB * SQ * DD];          // V pre-rounded to tf32
__device__ float    g_ctx[BB * SQ * DD];
__device__ float    g_bias[(size_t)BB * SQ * SQ]; // combined bias * log2(e)

// ---------------------------------------------------------------------------
// Precision helpers
// ---------------------------------------------------------------------------
__device__ __forceinline__ uint32_t f2tf(float f) {
    uint32_t u;
    asm("cvt.rna.tf32.f32 %0, %1;" : "=r"(u) : "f"(f));
    return u;
}
__device__ __forceinline__ uint32_t pack_bf2(float e0, float e1) {
    uint32_t r;
    asm("cvt.rn.bf16x2.f32 %0, %1, %2;" : "=r"(r) : "f"(e1), "f"(e0));
    return r;
}
__device__ __forceinline__ float bf2_lo_f(uint32_t p) { return __uint_as_float(p << 16); }
__device__ __forceinline__ float bf2_hi_f(uint32_t p) { return __uint_as_float(p & 0xffff0000u); }
__device__ __forceinline__ void split_bf2(float x, float y, uint32_t& hi, uint32_t& lo) {
    hi = pack_bf2(x, y);
    lo = pack_bf2(x - bf2_lo_f(hi), y - bf2_hi_f(hi));
}

__device__ __forceinline__ void mma_bf16(float c[4],
    uint32_t a0, uint32_t a1, uint32_t a2, uint32_t a3,
    uint32_t b0, uint32_t b1)
{
    asm volatile(
        "mma.sync.aligned.m16n8k16.row.col.f32.bf16.bf16.f32 "
        "{%0,%1,%2,%3}, {%4,%5,%6,%7}, {%8,%9}, {%0,%1,%2,%3};"
        : "+f"(c[0]), "+f"(c[1]), "+f"(c[2]), "+f"(c[3])
        : "r"(a0), "r"(a1), "r"(a2), "r"(a3), "r"(b0), "r"(b1));
}
__device__ __forceinline__ void mma_tf32(float c[4],
    uint32_t a0, uint32_t a1, uint32_t a2, uint32_t a3,
    uint32_t b0, uint32_t b1)
{
    asm volatile(
        "mma.sync.aligned.m16n8k8.row.col.f32.tf32.tf32.f32 "
        "{%0,%1,%2,%3}, {%4,%5,%6,%7}, {%8,%9}, {%0,%1,%2,%3};"
        : "+f"(c[0]), "+f"(c[1]), "+f"(c[2]), "+f"(c[3])
        : "r"(a0), "r"(a1), "r"(a2), "r"(a3), "r"(b0), "r"(b1));
}

// ldmatrix: four 8x8 b16 tiles, no-trans
__device__ __forceinline__ void ldsm_x4(uint32_t& r0, uint32_t& r1,
                                        uint32_t& r2, uint32_t& r3, uint32_t addr)
{
    asm volatile("ldmatrix.sync.aligned.m8n8.x4.shared.b16 {%0,%1,%2,%3}, [%4];"
        : "=r"(r0), "=r"(r1), "=r"(r2), "=r"(r3) : "r"(addr));
}

// cp.async helpers
__device__ __forceinline__ uint32_t smaddr(const void* p) {
    return (uint32_t)__cvta_generic_to_shared(p);
}
#define CP16(dst, src) asm volatile("cp.async.cg.shared.global [%0], [%1], 16;" :: "r"(dst), "l"(src))
#define CPCOMMIT()     asm volatile("cp.async.commit_group;")
#define CPWAIT(n)      asm volatile("cp.async.wait_group %0;" :: "n"(n))

// ---------------------------------------------------------------------------
// bf16x3 GEMM: C[M,N] = A[M,K] @ W[N,K]^T + bias[N]
// BM=128, BN=64, BK=32. 256 threads / 8 warps; warp = 16r x 64c.
// 2 CTAs/SM co-residency hides the convert/barrier phases.
// MODE epilogue: 0 = fp32 C, 1 = K split-bf16 words, 2 = V tf32 floats.
// ---------------------------------------------------------------------------
#define AP 20
#define GEMM_SMEM ((128 * AP * 2 + 64 * AP * 2) * 4)

template <int MODE>
__device__ __forceinline__ void gemm_tc_body(
    const float* __restrict__ A, const float* __restrict__ W,
    const float* __restrict__ bias, float* __restrict__ C,
    int m0, int n0)
{
    extern __shared__ uint32_t smu[];
    uint32_t* Ahi = smu;
    uint32_t* Alo = Ahi + 128 * AP;
    uint32_t* Whi = Alo + 128 * AP;
    uint32_t* Wlo = Whi + 64 * AP;

    const int tid = threadIdx.x;
    const int w = tid >> 5, lane = tid & 31;
    const int g = lane >> 2, t = lane & 3;

    float acc[8][4] = {};
    float2 pa[8], pw[4];

    #pragma unroll
    for (int i = 0; i < 8; i++) {
        int e = tid + i * 256;
        int r = e >> 4, c2 = e & 15;
        pa[i] = *(const float2*)&A[(size_t)(m0 + r) * DD + 2 * c2];
    }
    #pragma unroll
    for (int i = 0; i < 4; i++) {
        int e = tid + i * 256;
        int r = e >> 4, c2 = e & 15;
        pw[i] = *(const float2*)&W[(size_t)(n0 + r) * DD + 2 * c2];
    }

    for (int k0 = 0; k0 < DD; k0 += 32) {
        #pragma unroll
        for (int i = 0; i < 8; i++) {
            int e = tid + i * 256;
            int r = e >> 4, c2 = e & 15;
            split_bf2(pa[i].x, pa[i].y, Ahi[r * AP + c2], Alo[r * AP + c2]);
        }
        #pragma unroll
        for (int i = 0; i < 4; i++) {
            int e = tid + i * 256;
            int r = e >> 4, c2 = e & 15;
            split_bf2(pw[i].x, pw[i].y, Whi[r * AP + c2], Wlo[r * AP + c2]);
        }
        __syncthreads();

        if (k0 + 32 < DD) {
            #pragma unroll
            for (int i = 0; i < 8; i++) {
                int e = tid + i * 256;
                int r = e >> 4, c2 = e & 15;
                pa[i] = *(const float2*)&A[(size_t)(m0 + r) * DD + k0 + 32 + 2 * c2];
            }
            #pragma unroll
            for (int i = 0; i < 4; i++) {
                int e = tid + i * 256;
                int r = e >> 4, c2 = e & 15;
                pw[i] = *(const float2*)&W[(size_t)(n0 + r) * DD + k0 + 32 + 2 * c2];
            }
        }

        #pragma unroll
        for (int kk = 0; kk < 2; kk++) {
            const int ar = w * 16 + g, ac = kk * 8 + t;
            uint32_t ah0 = Ahi[ar * AP + ac];
            uint32_t ah1 = Ahi[(ar + 8) * AP + ac];
            uint32_t ah2 = Ahi[ar * AP + ac + 4];
            uint32_t ah3 = Ahi[(ar + 8) * AP + ac + 4];
            uint32_t al0 = Alo[ar * AP + ac];
            uint32_t al1 = Alo[(ar + 8) * AP + ac];
            uint32_t al2 = Alo[ar * AP + ac + 4];
            uint32_t al3 = Alo[(ar + 8) * AP + ac + 4];
            #pragma unroll
            for (int ns = 0; ns < 8; ns++) {
                const int br = ns * 8 + g, bc = kk * 8 + t;
                uint32_t bh0 = Whi[br * AP + bc];
                uint32_t bh1 = Whi[br * AP + bc + 4];
                uint32_t bl0 = Wlo[br * AP + bc];
                uint32_t bl1 = Wlo[br * AP + bc + 4];
                mma_bf16(acc[ns], ah0, ah1, ah2, ah3, bh0, bh1);
                mma_bf16(acc[ns], ah0, ah1, ah2, ah3, bl0, bl1);
                mma_bf16(acc[ns], al0, al1, al2, al3, bh0, bh1);
            }
        }
        __syncthreads();
    }

    // Epilogue
    #pragma unroll
    for (int ns = 0; ns < 8; ns++) {
        int n = n0 + ns * 8 + 2 * t;
        float b0 = bias[n], b1 = bias[n + 1];
        int r = m0 + w * 16 + g;
        float v00 = acc[ns][0] + b0, v01 = acc[ns][1] + b1;
        float v10 = acc[ns][2] + b0, v11 = acc[ns][3] + b1;
        if (MODE == 0) {
            *(float2*)&C[(size_t)r * DD + n] = make_float2(v00, v01);
            *(float2*)&C[(size_t)(r + 8) * DD + n] = make_float2(v10, v11);
        } else if (MODE == 1) {
            uint32_t hi0, lo0, hi1, lo1;
            split_bf2(v00, v01, hi0, lo0);
            split_bf2(v10, v11, hi1, lo1);
            size_t wcol = (size_t)(n >> 1);
            g_Khw[(size_t)r * (DD / 2) + wcol] = hi0;
            g_Klw[(size_t)r * (DD / 2) + wcol] = lo0;
            g_Khw[(size_t)(r + 8) * (DD / 2) + wcol] = hi1;
            g_Klw[(size_t)(r + 8) * (DD / 2) + wcol] = lo1;
        } else {
            *(float2*)&g_Vt[(size_t)r * DD + n] =
                make_float2(__uint_as_float(f2tf(v00)), __uint_as_float(f2tf(v01)));
            *(float2*)&g_Vt[(size_t)(r + 8) * DD + n] =
                make_float2(__uint_as_float(f2tf(v10)), __uint_as_float(f2tf(v11)));
        }
    }
}

// ---------------------------------------------------------------------------
// Fused QKV + bias kernel. z in {0,1,2}: GEMM planes. z == 3: combined bias.
// ---------------------------------------------------------------------------
__global__ __launch_bounds__(256, 2) void qkv_bias_kernel(
    const float* __restrict__ x,
    const float* __restrict__ Wq, const float* __restrict__ bq,
    const float* __restrict__ Wk, const float* __restrict__ bk,
    const float* __restrict__ Wv, const float* __restrict__ bv,
    const float* __restrict__ ipa, const float* __restrict__ assoc,
    const float* __restrict__ amask,
    const int* __restrict__ cid, const unsigned char* __restrict__ kpm)
{
    int m0 = blockIdx.y * 128, n0 = blockIdx.x * 64;
    if (blockIdx.z == 0) {
        gemm_tc_body<0>(x, Wq, bq, g_Q, m0, n0);
    } else if (blockIdx.z == 1) {
        gemm_tc_body<1>(x, Wk, bk, nullptr, m0, n0);
    } else if (blockIdx.z == 2) {
        gemm_tc_body<2>(x, Wv, bv, nullptr, m0, n0);
    } else {
        // Bias plane: grid-stride float4 over BB*SQ*SQ elements
        const int nthreads = gridDim.x * gridDim.y * 256;   // 65536
        const int tglob = (blockIdx.y * gridDim.x + blockIdx.x) * 256 + threadIdx.x;
        const int npacks = (BB * SQ * SQ) / 4;              // 2097152
        for (int p = tglob; p < npacks; p += nthreads) {
            int idx = p * 4;
            int k4 = idx & (SQ - 1);
            int t2 = idx >> 11;
            int q = t2 & (SQ - 1);
            int b = t2 >> 11;

            float4 vi = *(const float4*)&ipa[idx];
            float4 va = *(const float4*)&assoc[idx];
            float4 vm = *(const float4*)&amask[q * SQ + k4];
            int4 ck4 = *(const int4*)&cid[b * SQ + k4];
            uchar4 kp4 = *(const uchar4*)&kpm[b * SQ + k4];
            int cq = cid[b * SQ + q];
            bool qv = cq >= 0;

            float r0 = vi.x + va.x + vm.x;
            float r1 = vi.y + va.y + vm.y;
            float r2 = vi.z + va.z + vm.z;
            float r3 = vi.w + va.w + vm.w;
            if (qv && cq == ck4.x && q != k4)     r0 += CBIAS;
            if (qv && cq == ck4.y && q != k4 + 1) r1 += CBIAS;
            if (qv && cq == ck4.z && q != k4 + 2) r2 += CBIAS;
            if (qv && cq == ck4.w && q != k4 + 3) r3 += CBIAS;
            if (kp4.x) r0 = -1e30f;
            if (kp4.y) r1 = -1e30f;
            if (kp4.z) r2 = -1e30f;
            if (kp4.w) r3 = -1e30f;
            *(float4*)&g_bias[idx] = make_float4(r0 * LOG2E, r1 * LOG2E,
                                                 r2 * LOG2E, r3 * LOG2E);
        }
    }
}

__global__ __launch_bounds__(256, 2) void proj_tc_kernel(
    const float* __restrict__ Wo, const float* __restrict__ bo,
    float* __restrict__ out)
{
    gemm_tc_body<0>(g_ctx, Wo, bo, out, blockIdx.y * 128, blockIdx.x * 64);
}

// ---------------------------------------------------------------------------
// Tensor-core flash attention with cp.async 2-stage K/V pipeline.
// QK B-operands fetched via ldmatrix.x4 (4x fewer smem instructions).
// exp2 softmax; PV tf32 single-pass.
// ---------------------------------------------------------------------------
#define KP 36
#define VP 72
#define PP 68
#define KSTG (64 * KP)
#define VSTG (64 * VP)
#define ATTN_SMEM ((2 * KSTG * 2 + 2 * VSTG + 128 * PP) * 4)
#define NKT (SQ / 64)

__global__ __launch_bounds__(256, 2) void attn_tc_kernel()
{
    extern __shared__ uint32_t smu[];
    uint32_t* KhiS = smu;                       // 2 stages
    uint32_t* KloS = KhiS + 2 * KSTG;
    float* VsS = (float*)(KloS + 2 * KSTG);     // 2 stages
    float* Ps  = VsS + 2 * VSTG;                // 128*PP

    const int tid = threadIdx.x;
    const int w = tid >> 5, lane = tid & 31;
    const int g = lane >> 2, t = lane & 3;
    const int q0 = blockIdx.x * 128;
    const int h  = blockIdx.y;
    const int b  = blockIdx.z;

    const uint32_t* KHsrc = g_Khw + (size_t)b * SQ * (DD / 2) + h * (HD / 2);
    const uint32_t* KLsrc = g_Klw + (size_t)b * SQ * (DD / 2) + h * (HD / 2);
    const float*    Vsrc  = g_Vt  + (size_t)b * SQ * DD + h * HD;

    // ldmatrix lane->address components (x4: matrix m = lane/8, row = lane%8)
    const int lm_m = lane >> 3, lm_r = lane & 7;

    // -- issue tile 0 loads immediately (overlap Q staging) --
    {
        #pragma unroll
        for (int i = 0; i < 2; i++) {
            int e = tid + i * 256;
            int r = e >> 3, c4 = (e & 7) * 4;
            CP16(smaddr(KhiS + r * KP + c4), KHsrc + (size_t)r * (DD / 2) + c4);
            CP16(smaddr(KloS + r * KP + c4), KLsrc + (size_t)r * (DD / 2) + c4);
        }
        #pragma unroll
        for (int i = 0; i < 4; i++) {
            int e = tid + i * 256;
            int r = e >> 4, c4 = (e & 15) * 4;
            CP16(smaddr(VsS + r * VP + c4), Vsrc + (size_t)r * DD + c4);
        }
        CPCOMMIT();
    }

    // ---- Stage Q tile into Ps, build persistent bf16 A-fragments ----
    const float* Qg = g_Q + ((size_t)b * SQ + q0) * DD + h * HD;
    #pragma unroll
    for (int i = 0; i < 32; i++) {
        int e = tid + i * 256;
        int r = e >> 6, c = e & 63;
        Ps[r * PP + c] = Qg[(size_t)r * DD + c];
    }
    __syncthreads();

    uint32_t qh[4][4], ql[4][4];
    #pragma unroll
    for (int kk = 0; kk < 4; kk++) {
        #pragma unroll
        for (int i = 0; i < 4; i++) {
            int r = w * 16 + g + (i & 1) * 8;
            int c = kk * 16 + 2 * t + (i >> 1) * 8;
            float x = Ps[r * PP + c] * SCALE_L2E;
            float y = Ps[r * PP + c + 1] * SCALE_L2E;
            split_bf2(x, y, qh[kk][i], ql[kk][i]);
        }
    }
    __syncthreads();

    float mrow[2] = { -1e30f, -1e30f };
    float lrow[2] = { 0.0f, 0.0f };
    float o[8][4] = {};

    const float* Bg = g_bias + ((size_t)b * SQ + q0) * SQ;

    for (int kt = 0; kt < NKT; kt++) {
        if (kt + 1 < NKT) {
            int s = (kt + 1) & 1;
            int k0n = (kt + 1) * 64;
            #pragma unroll
            for (int i = 0; i < 2; i++) {
                int e = tid + i * 256;
                int r = e >> 3, c4 = (e & 7) * 4;
                CP16(smaddr(KhiS + s * KSTG + r * KP + c4),
                     KHsrc + (size_t)(k0n + r) * (DD / 2) + c4);
                CP16(smaddr(KloS + s * KSTG + r * KP + c4),
                     KLsrc + (size_t)(k0n + r) * (DD / 2) + c4);
            }
            #pragma unroll
            for (int i = 0; i < 4; i++) {
                int e = tid + i * 256;
                int r = e >> 4, c4 = (e & 15) * 4;
                CP16(smaddr(VsS + s * VSTG + r * VP + c4),
                     Vsrc + (size_t)(k0n + r) * DD + c4);
            }
            CPCOMMIT();
            CPWAIT(1);
        } else {
            CPWAIT(0);
        }
        __syncthreads();

        const uint32_t* Khi = KhiS + (kt & 1) * KSTG;
        const uint32_t* Klo = KloS + (kt & 1) * KSTG;
        const float*    Vs  = VsS  + (kt & 1) * VSTG;
        const int k0 = kt * 64;

        // ---- Bias loads early (hidden behind QK MMAs) ----
        float2 bq0[8], bq1[8];
        #pragma unroll
        for (int ns = 0; ns < 8; ns++) {
            int col = k0 + ns * 8 + 2 * t;
            bq0[ns] = *(const float2*)&Bg[(size_t)(w * 16 + g) * SQ + col];
            bq1[ns] = *(const float2*)&Bg[(size_t)(w * 16 + g + 8) * SQ + col];
        }

        // ---- S = Q @ K^T (bf16x3, B-frags via ldmatrix.x4) ----
        float s[8][4] = {};
        #pragma unroll
        for (int kk = 0; kk < 4; kk++) {
            #pragma unroll
            for (int np = 0; np < 4; np++) {   // ns pair = (2np, 2np+1)
                // lane m=0..3: matrices (ns=2np+m/2, word offset (m&1)*4)
                uint32_t a_hi = smaddr(Khi + ((2 * np + (lm_m >> 1)) * 8 + lm_r) * KP
                                           + kk * 8 + (lm_m & 1) * 4);
                uint32_t a_lo = smaddr(Klo + ((2 * np + (lm_m >> 1)) * 8 + lm_r) * KP
                                           + kk * 8 + (lm_m & 1) * 4);
                uint32_t bh0a, bh1a, bh0b, bh1b, bl0a, bl1a, bl0b, bl1b;
                ldsm_x4(bh0a, bh1a, bh0b, bh1b, a_hi);
                ldsm_x4(bl0a, bl1a, bl0b, bl1b, a_lo);
                mma_bf16(s[2*np],   qh[kk][0], qh[kk][1], qh[kk][2], qh[kk][3], bh0a, bh1a);
                mma_bf16(s[2*np],   qh[kk][0], qh[kk][1], qh[kk][2], qh[kk][3], bl0a, bl1a);
                mma_bf16(s[2*np],   ql[kk][0], ql[kk][1], ql[kk][2], ql[kk][3], bh0a, bh1a);
                mma_bf16(s[2*np+1], qh[kk][0], qh[kk][1], qh[kk][2], qh[kk][3], bh0b, bh1b);
                mma_bf16(s[2*np+1], qh[kk][0], qh[kk][1], qh[kk][2], qh[kk][3], bl0b, bl1b);
                mma_bf16(s[2*np+1], ql[kk][0], ql[kk][1], ql[kk][2], ql[kk][3], bh0b, bh1b);
            }
        }

        #pragma unroll
        for (int ns = 0; ns < 8; ns++) {
            s[ns][0] += bq0[ns].x; s[ns][1] += bq0[ns].y;
            s[ns][2] += bq1[ns].x; s[ns][3] += bq1[ns].y;
        }

        // ---- Online softmax (exp2, registers + quad shfl) ----
        float tm0 = -1e30f, tm1 = -1e30f;
        #pragma unroll
        for (int ns = 0; ns < 8; ns++) {
            tm0 = fmaxf(tm0, fmaxf(s[ns][0], s[ns][1]));
            tm1 = fmaxf(tm1, fmaxf(s[ns][2], s[ns][3]));
        }
        tm0 = fmaxf(tm0, __shfl_xor_sync(0xffffffffu, tm0, 1));
        tm0 = fmaxf(tm0, __shfl_xor_sync(0xffffffffu, tm0, 2));
        tm1 = fmaxf(tm1, __shfl_xor_sync(0xffffffffu, tm1, 1));
        tm1 = fmaxf(tm1, __shfl_xor_sync(0xffffffffu, tm1, 2));

        float mn0 = fmaxf(mrow[0], tm0), mn1 = fmaxf(mrow[1], tm1);
        float cr0 = exp2f(mrow[0] - mn0), cr1 = exp2f(mrow[1] - mn1);
        float sum0 = 0.0f, sum1 = 0.0f;
        const int prow = w * 16 + g;
        #pragma unroll
        for (int ns = 0; ns < 8; ns++) {
            float p0 = exp2f(s[ns][0] - mn0);
            float p1 = exp2f(s[ns][1] - mn0);
            float p2 = exp2f(s[ns][2] - mn1);
            float p3 = exp2f(s[ns][3] - mn1);
            sum0 += p0 + p1; sum1 += p2 + p3;
            int pc = ns * 8 + 2 * t;
            Ps[prow * PP + pc]           = p0;   // raw fp32; tf32 MMA truncates
            Ps[prow * PP + pc + 1]       = p1;
            Ps[(prow + 8) * PP + pc]     = p2;
            Ps[(prow + 8) * PP + pc + 1] = p3;
            o[ns][0] *= cr0; o[ns][1] *= cr0;
            o[ns][2] *= cr1; o[ns][3] *= cr1;
        }
        sum0 += __shfl_xor_sync(0xffffffffu, sum0, 1);
        sum0 += __shfl_xor_sync(0xffffffffu, sum0, 2);
        sum1 += __shfl_xor_sync(0xffffffffu, sum1, 1);
        sum1 += __shfl_xor_sync(0xffffffffu, sum1, 2);
        lrow[0] = lrow[0] * cr0 + sum0;
        lrow[1] = lrow[1] * cr1 + sum1;
        mrow[0] = mn0; mrow[1] = mn1;
        __syncwarp();

        // ---- O += P @ V (tf32 single-pass) ----
        #pragma unroll
        for (int kk = 0; kk < 8; kk++) {
            uint32_t a0 = __float_as_uint(Ps[prow * PP + kk * 8 + t]);
            uint32_t a1 = __float_as_uint(Ps[(prow + 8) * PP + kk * 8 + t]);
            uint32_t a2 = __float_as_uint(Ps[prow * PP + kk * 8 + t + 4]);
            uint32_t a3 = __float_as_uint(Ps[(prow + 8) * PP + kk * 8 + t + 4]);
            #pragma unroll
            for (int ns = 0; ns < 8; ns++) {
                uint32_t b0 = __float_as_uint(Vs[(kk * 8 + t) * VP + ns * 8 + g]);
                uint32_t b1 = __float_as_uint(Vs[(kk * 8 + t + 4) * VP + ns * 8 + g]);
                mma_tf32(o[ns], a0, a1, a2, a3, b0, b1);
            }
        }
        __syncthreads();
    }

    // ---- Normalize + write ctx ----
    float inv0 = 1.0f / lrow[0], inv1 = 1.0f / lrow[1];
    float* Cg = g_ctx + ((size_t)b * SQ + q0) * DD + h * HD;
    #pragma unroll
    for (int ns = 0; ns < 8; ns++) {
        int col = ns * 8 + 2 * t;
        float2 v0 = make_float2(o[ns][0] * inv0, o[ns][1] * inv0);
        float2 v1 = make_float2(o[ns][2] * inv1, o[ns][3] * inv1);
        *(float2*)&Cg[(size_t)(w * 16 + g) * DD + col] = v0;
        *(float2*)&Cg[(size_t)(w * 16 + g + 8) * DD + col] = v1;
    }
}

// ---------------------------------------------------------------------------
extern "C" void kernel_launch(void* const* d_in, const int* in_sizes, int n_in,
                              void* d_out, int out_size)
{
    const float* x     = (const float*)d_in[0];
    const float* Wq    = (const float*)d_in[1];
    const float* bq    = (const float*)d_in[2];
    const float* Wk    = (const float*)d_in[3];
    const float* bk    = (const float*)d_in[4];
    const float* Wv    = (const float*)d_in[5];
    const float* bv    = (const float*)d_in[6];
    const float* Wo    = (const float*)d_in[7];
    const float* bo    = (const float*)d_in[8];
    const float* amask = (const float*)d_in[9];
    const float* ipa   = (const float*)d_in[10];
    const float* assoc = (const float*)d_in[11];
    const int* cid            = (const int*)d_in[12];       // int32 (JAX x64 off)
    const unsigned char* kpm  = (const unsigned char*)d_in[13];
    float* out = (float*)d_out;

    cudaFuncSetAttribute(attn_tc_kernel, cudaFuncAttributeMaxDynamicSharedMemorySize, ATTN_SMEM);

    // Fused QKV projections + combined bias (z = 3 plane)
    qkv_bias_kernel<<<dim3(DD / 64, (BB * SQ) / 128, 4), 256, GEMM_SMEM>>>(
        x, Wq, bq, Wk, bk, Wv, bv, ipa, assoc, amask, cid, kpm);

    // Tensor-core flash attention (2 CTAs/SM, cp.async pipelined)
    attn_tc_kernel<<<dim3(SQ / 128, NH, BB), 256, ATTN_SMEM>>>();

    // Output projection
    proj_tc_kernel<<<dim3(DD / 64, (BB * SQ) / 128), 256, GEMM_SMEM>>>(Wo, bo, out);
}

// round 11
// speedup vs baseline: 4.1705x; 1.0318x over previous
#include <cuda_runtime.h>
#include <math.h>
#include <stdint.h>

// Problem constants
#define BB 2
#define SQ 2048
#define DD 512
#define NH 8
#define HD 64
#define SCALE 0.125f   // 1/sqrt(64)
#define CBIAS 0.5f
#define LOG2E 1.4426950408889634f
#define SCALE_L2E (SCALE * LOG2E)

// Scratch (device globals; no allocation allowed)
__device__ float    g_Q[BB * SQ * DD];
__device__ uint32_t g_Khw[BB * SQ * (DD / 2)];   // K as packed bf16x2 (hi)
__device__ uint32_t g_Klw[BB * SQ * (DD / 2)];   // K residual (lo)
__device__ float    g_Vt[BB * SQ * DD];          // V pre-rounded to tf32
__device__ float    g_ctx[BB * SQ * DD];
__device__ float    g_bias[(size_t)BB * SQ * SQ]; // combined bias * log2(e)

// ---------------------------------------------------------------------------
// Precision helpers
// ---------------------------------------------------------------------------
__device__ __forceinline__ uint32_t f2tf(float f) {
    uint32_t u;
    asm("cvt.rna.tf32.f32 %0, %1;" : "=r"(u) : "f"(f));
    return u;
}
__device__ __forceinline__ uint32_t pack_bf2(float e0, float e1) {
    uint32_t r;
    asm("cvt.rn.bf16x2.f32 %0, %1, %2;" : "=r"(r) : "f"(e1), "f"(e0));
    return r;
}
__device__ __forceinline__ float bf2_lo_f(uint32_t p) { return __uint_as_float(p << 16); }
__device__ __forceinline__ float bf2_hi_f(uint32_t p) { return __uint_as_float(p & 0xffff0000u); }
__device__ __forceinline__ void split_bf2(float x, float y, uint32_t& hi, uint32_t& lo) {
    hi = pack_bf2(x, y);
    lo = pack_bf2(x - bf2_lo_f(hi), y - bf2_hi_f(hi));
}

__device__ __forceinline__ void mma_bf16(float c[4],
    uint32_t a0, uint32_t a1, uint32_t a2, uint32_t a3,
    uint32_t b0, uint32_t b1)
{
    asm volatile(
        "mma.sync.aligned.m16n8k16.row.col.f32.bf16.bf16.f32 "
        "{%0,%1,%2,%3}, {%4,%5,%6,%7}, {%8,%9}, {%0,%1,%2,%3};"
        : "+f"(c[0]), "+f"(c[1]), "+f"(c[2]), "+f"(c[3])
        : "r"(a0), "r"(a1), "r"(a2), "r"(a3), "r"(b0), "r"(b1));
}
__device__ __forceinline__ void mma_tf32(float c[4],
    uint32_t a0, uint32_t a1, uint32_t a2, uint32_t a3,
    uint32_t b0, uint32_t b1)
{
    asm volatile(
        "mma.sync.aligned.m16n8k8.row.col.f32.tf32.tf32.f32 "
        "{%0,%1,%2,%3}, {%4,%5,%6,%7}, {%8,%9}, {%0,%1,%2,%3};"
        : "+f"(c[0]), "+f"(c[1]), "+f"(c[2]), "+f"(c[3])
        : "r"(a0), "r"(a1), "r"(a2), "r"(a3), "r"(b0), "r"(b1));
}

// ldmatrix: four 8x8 b16 tiles, no-trans
__device__ __forceinline__ void ldsm_x4(uint32_t& r0, uint32_t& r1,
                                        uint32_t& r2, uint32_t& r3, uint32_t addr)
{
    asm volatile("ldmatrix.sync.aligned.m8n8.x4.shared.b16 {%0,%1,%2,%3}, [%4];"
        : "=r"(r0), "=r"(r1), "=r"(r2), "=r"(r3) : "r"(addr));
}

// cp.async helpers
__device__ __forceinline__ uint32_t smaddr(const void* p) {
    return (uint32_t)__cvta_generic_to_shared(p);
}
#define CP16(dst, src) asm volatile("cp.async.cg.shared.global [%0], [%1], 16;" :: "r"(dst), "l"(src))
#define CPCOMMIT()     asm volatile("cp.async.commit_group;")
#define CPWAIT(n)      asm volatile("cp.async.wait_group %0;" :: "n"(n))

// ---------------------------------------------------------------------------
// bf16x3 GEMM: C[M,N] = A[M,K] @ W[N,K]^T + bias[N]
// BM=128, BN=64, BK=32. 256 threads / 8 warps; warp = 16r x 64c.
// All MMA fragments fetched via ldmatrix.x4 (4x fewer L1 instructions).
// MODE epilogue: 0 = fp32 C, 1 = K split-bf16 words, 2 = V tf32 floats.
// ---------------------------------------------------------------------------
#define AP 20
#define GEMM_SMEM ((128 * AP * 2 + 64 * AP * 2) * 4)

template <int MODE>
__device__ __forceinline__ void gemm_tc_body(
    const float* __restrict__ A, const float* __restrict__ W,
    const float* __restrict__ bias, float* __restrict__ C,
    int m0, int n0)
{
    extern __shared__ uint32_t smu[];
    uint32_t* Ahi = smu;
    uint32_t* Alo = Ahi + 128 * AP;
    uint32_t* Whi = Alo + 128 * AP;
    uint32_t* Wlo = Whi + 64 * AP;

    const int tid = threadIdx.x;
    const int w = tid >> 5, lane = tid & 31;
    const int g = lane >> 2, t = lane & 3;
    const int lm_m = lane >> 3, lm_r = lane & 7;

    float acc[8][4] = {};
    float2 pa[8], pw[4];

    #pragma unroll
    for (int i = 0; i < 8; i++) {
        int e = tid + i * 256;
        int r = e >> 4, c2 = e & 15;
        pa[i] = *(const float2*)&A[(size_t)(m0 + r) * DD + 2 * c2];
    }
    #pragma unroll
    for (int i = 0; i < 4; i++) {
        int e = tid + i * 256;
        int r = e >> 4, c2 = e & 15;
        pw[i] = *(const float2*)&W[(size_t)(n0 + r) * DD + 2 * c2];
    }

    for (int k0 = 0; k0 < DD; k0 += 32) {
        #pragma unroll
        for (int i = 0; i < 8; i++) {
            int e = tid + i * 256;
            int r = e >> 4, c2 = e & 15;
            split_bf2(pa[i].x, pa[i].y, Ahi[r * AP + c2], Alo[r * AP + c2]);
        }
        #pragma unroll
        for (int i = 0; i < 4; i++) {
            int e = tid + i * 256;
            int r = e >> 4, c2 = e & 15;
            split_bf2(pw[i].x, pw[i].y, Whi[r * AP + c2], Wlo[r * AP + c2]);
        }
        __syncthreads();

        if (k0 + 32 < DD) {
            #pragma unroll
            for (int i = 0; i < 8; i++) {
                int e = tid + i * 256;
                int r = e >> 4, c2 = e & 15;
                pa[i] = *(const float2*)&A[(size_t)(m0 + r) * DD + k0 + 32 + 2 * c2];
            }
            #pragma unroll
            for (int i = 0; i < 4; i++) {
                int e = tid + i * 256;
                int r = e >> 4, c2 = e & 15;
                pw[i] = *(const float2*)&W[(size_t)(n0 + r) * DD + k0 + 32 + 2 * c2];
            }
        }

        #pragma unroll
        for (int kk = 0; kk < 2; kk++) {
            // A fragments (16x16 tile = one ldsm.x4 each for hi/lo)
            uint32_t ah0, ah1, ah2, ah3, al0, al1, al2, al3;
            {
                int arow = w * 16 + (lm_m & 1) * 8 + lm_r;
                int acol = kk * 8 + (lm_m >> 1) * 4;
                ldsm_x4(ah0, ah1, ah2, ah3, smaddr(Ahi + arow * AP + acol));
                ldsm_x4(al0, al1, al2, al3, smaddr(Alo + arow * AP + acol));
            }
            #pragma unroll
            for (int np = 0; np < 4; np++) {
                int brow = (2 * np + (lm_m >> 1)) * 8 + lm_r;
                int bcol = kk * 8 + (lm_m & 1) * 4;
                uint32_t bh0, bh1, bh2, bh3, bl0, bl1, bl2, bl3;
                ldsm_x4(bh0, bh1, bh2, bh3, smaddr(Whi + brow * AP + bcol));
                ldsm_x4(bl0, bl1, bl2, bl3, smaddr(Wlo + brow * AP + bcol));
                mma_bf16(acc[2*np],   ah0, ah1, ah2, ah3, bh0, bh1);
                mma_bf16(acc[2*np],   ah0, ah1, ah2, ah3, bl0, bl1);
                mma_bf16(acc[2*np],   al0, al1, al2, al3, bh0, bh1);
                mma_bf16(acc[2*np+1], ah0, ah1, ah2, ah3, bh2, bh3);
                mma_bf16(acc[2*np+1], ah0, ah1, ah2, ah3, bl2, bl3);
                mma_bf16(acc[2*np+1], al0, al1, al2, al3, bh2, bh3);
            }
        }
        __syncthreads();
    }

    // Epilogue
    #pragma unroll
    for (int ns = 0; ns < 8; ns++) {
        int n = n0 + ns * 8 + 2 * t;
        float b0 = bias[n], b1 = bias[n + 1];
        int r = m0 + w * 16 + g;
        float v00 = acc[ns][0] + b0, v01 = acc[ns][1] + b1;
        float v10 = acc[ns][2] + b0, v11 = acc[ns][3] + b1;
        if (MODE == 0) {
            *(float2*)&C[(size_t)r * DD + n] = make_float2(v00, v01);
            *(float2*)&C[(size_t)(r + 8) * DD + n] = make_float2(v10, v11);
        } else if (MODE == 1) {
            uint32_t hi0, lo0, hi1, lo1;
            split_bf2(v00, v01, hi0, lo0);
            split_bf2(v10, v11, hi1, lo1);
            size_t wcol = (size_t)(n >> 1);
            g_Khw[(size_t)r * (DD / 2) + wcol] = hi0;
            g_Klw[(size_t)r * (DD / 2) + wcol] = lo0;
            g_Khw[(size_t)(r + 8) * (DD / 2) + wcol] = hi1;
            g_Klw[(size_t)(r + 8) * (DD / 2) + wcol] = lo1;
        } else {
            *(float2*)&g_Vt[(size_t)r * DD + n] =
                make_float2(__uint_as_float(f2tf(v00)), __uint_as_float(f2tf(v01)));
            *(float2*)&g_Vt[(size_t)(r + 8) * DD + n] =
                make_float2(__uint_as_float(f2tf(v10)), __uint_as_float(f2tf(v11)));
        }
    }
}

// ---------------------------------------------------------------------------
// Fused QKV + bias kernel. z in {0,1,2}: GEMM planes. z == 3: combined bias.
// ---------------------------------------------------------------------------
__global__ __launch_bounds__(256, 2) void qkv_bias_kernel(
    const float* __restrict__ x,
    const float* __restrict__ Wq, const float* __restrict__ bq,
    const float* __restrict__ Wk, const float* __restrict__ bk,
    const float* __restrict__ Wv, const float* __restrict__ bv,
    const float* __restrict__ ipa, const float* __restrict__ assoc,
    const float* __restrict__ amask,
    const int* __restrict__ cid, const unsigned char* __restrict__ kpm)
{
    int m0 = blockIdx.y * 128, n0 = blockIdx.x * 64;
    if (blockIdx.z == 0) {
        gemm_tc_body<0>(x, Wq, bq, g_Q, m0, n0);
    } else if (blockIdx.z == 1) {
        gemm_tc_body<1>(x, Wk, bk, nullptr, m0, n0);
    } else if (blockIdx.z == 2) {
        gemm_tc_body<2>(x, Wv, bv, nullptr, m0, n0);
    } else {
        // Bias plane: grid-stride float4 over BB*SQ*SQ elements
        const int nthreads = gridDim.x * gridDim.y * 256;   // 65536
        const int tglob = (blockIdx.y * gridDim.x + blockIdx.x) * 256 + threadIdx.x;
        const int npacks = (BB * SQ * SQ) / 4;              // 2097152
        for (int p = tglob; p < npacks; p += nthreads) {
            int idx = p * 4;
            int k4 = idx & (SQ - 1);
            int t2 = idx >> 11;
            int q = t2 & (SQ - 1);
            int b = t2 >> 11;

            float4 vi = *(const float4*)&ipa[idx];
            float4 va = *(const float4*)&assoc[idx];
            float4 vm = *(const float4*)&amask[q * SQ + k4];
            int4 ck4 = *(const int4*)&cid[b * SQ + k4];
            uchar4 kp4 = *(const uchar4*)&kpm[b * SQ + k4];
            int cq = cid[b * SQ + q];
            bool qv = cq >= 0;

            float r0 = vi.x + va.x + vm.x;
            float r1 = vi.y + va.y + vm.y;
            float r2 = vi.z + va.z + vm.z;
            float r3 = vi.w + va.w + vm.w;
            if (qv && cq == ck4.x && q != k4)     r0 += CBIAS;
            if (qv && cq == ck4.y && q != k4 + 1) r1 += CBIAS;
            if (qv && cq == ck4.z && q != k4 + 2) r2 += CBIAS;
            if (qv && cq == ck4.w && q != k4 + 3) r3 += CBIAS;
            if (kp4.x) r0 = -1e30f;
            if (kp4.y) r1 = -1e30f;
            if (kp4.z) r2 = -1e30f;
            if (kp4.w) r3 = -1e30f;
            *(float4*)&g_bias[idx] = make_float4(r0 * LOG2E, r1 * LOG2E,
                                                 r2 * LOG2E, r3 * LOG2E);
        }
    }
}

__global__ __launch_bounds__(256, 2) void proj_tc_kernel(
    const float* __restrict__ Wo, const float* __restrict__ bo,
    float* __restrict__ out)
{
    gemm_tc_body<0>(g_ctx, Wo, bo, out, blockIdx.y * 128, blockIdx.x * 64);
}

// ---------------------------------------------------------------------------
// Tensor-core flash attention, cp.async 2-stage pipeline, ONE barrier/tile.
// QK B-operands via ldmatrix.x4; exp2 softmax; PV tf32 single-pass.
// ---------------------------------------------------------------------------
#define KP 36
#define VP 72
#define PP 68
#define KSTG (64 * KP)
#define VSTG (64 * VP)
#define ATTN_SMEM ((2 * KSTG * 2 + 2 * VSTG + 128 * PP) * 4)
#define NKT (SQ / 64)

__global__ __launch_bounds__(256, 2) void attn_tc_kernel()
{
    extern __shared__ uint32_t smu[];
    uint32_t* KhiS = smu;                       // 2 stages
    uint32_t* KloS = KhiS + 2 * KSTG;
    float* VsS = (float*)(KloS + 2 * KSTG);     // 2 stages
    float* Ps  = VsS + 2 * VSTG;                // 128*PP

    const int tid = threadIdx.x;
    const int w = tid >> 5, lane = tid & 31;
    const int g = lane >> 2, t = lane & 3;
    const int q0 = blockIdx.x * 128;
    const int h  = blockIdx.y;
    const int b  = blockIdx.z;

    const uint32_t* KHsrc = g_Khw + (size_t)b * SQ * (DD / 2) + h * (HD / 2);
    const uint32_t* KLsrc = g_Klw + (size_t)b * SQ * (DD / 2) + h * (HD / 2);
    const float*    Vsrc  = g_Vt  + (size_t)b * SQ * DD + h * HD;

    const int lm_m = lane >> 3, lm_r = lane & 7;

    // -- issue tile 0 loads immediately (overlap Q staging) --
    {
        #pragma unroll
        for (int i = 0; i < 2; i++) {
            int e = tid + i * 256;
            int r = e >> 3, c4 = (e & 7) * 4;
            CP16(smaddr(KhiS + r * KP + c4), KHsrc + (size_t)r * (DD / 2) + c4);
            CP16(smaddr(KloS + r * KP + c4), KLsrc + (size_t)r * (DD / 2) + c4);
        }
        #pragma unroll
        for (int i = 0; i < 4; i++) {
            int e = tid + i * 256;
            int r = e >> 4, c4 = (e & 15) * 4;
            CP16(smaddr(VsS + r * VP + c4), Vsrc + (size_t)r * DD + c4);
        }
        CPCOMMIT();
    }

    // ---- Stage Q tile into Ps, build persistent bf16 A-fragments ----
    const float* Qg = g_Q + ((size_t)b * SQ + q0) * DD + h * HD;
    #pragma unroll
    for (int i = 0; i < 32; i++) {
        int e = tid + i * 256;
        int r = e >> 6, c = e & 63;
        Ps[r * PP + c] = Qg[(size_t)r * DD + c];
    }
    __syncthreads();

    uint32_t qh[4][4], ql[4][4];
    #pragma unroll
    for (int kk = 0; kk < 4; kk++) {
        #pragma unroll
        for (int i = 0; i < 4; i++) {
            int r = w * 16 + g + (i & 1) * 8;
            int c = kk * 16 + 2 * t + (i >> 1) * 8;
            float x = Ps[r * PP + c] * SCALE_L2E;
            float y = Ps[r * PP + c + 1] * SCALE_L2E;
            split_bf2(x, y, qh[kk][i], ql[kk][i]);
        }
    }

    float mrow[2] = { -1e30f, -1e30f };
    float lrow[2] = { 0.0f, 0.0f };
    float o[8][4] = {};

    const float* Bg = g_bias + ((size_t)b * SQ + q0) * SQ;

    for (int kt = 0; kt < NKT; kt++) {
        CPWAIT(0);          // this tile's cp.async data has arrived
        __syncthreads();    // publish it + all warps done with stage (kt+1)&1

        // Issue next tile into the stage every warp just finished with
        if (kt + 1 < NKT) {
            int s = (kt + 1) & 1;
            int k0n = (kt + 1) * 64;
            #pragma unroll
            for (int i = 0; i < 2; i++) {
                int e = tid + i * 256;
                int r = e >> 3, c4 = (e & 7) * 4;
                CP16(smaddr(KhiS + s * KSTG + r * KP + c4),
                     KHsrc + (size_t)(k0n + r) * (DD / 2) + c4);
                CP16(smaddr(KloS + s * KSTG + r * KP + c4),
                     KLsrc + (size_t)(k0n + r) * (DD / 2) + c4);
            }
            #pragma unroll
            for (int i = 0; i < 4; i++) {
                int e = tid + i * 256;
                int r = e >> 4, c4 = (e & 15) * 4;
                CP16(smaddr(VsS + s * VSTG + r * VP + c4),
                     Vsrc + (size_t)(k0n + r) * DD + c4);
            }
            CPCOMMIT();
        }

        const uint32_t* Khi = KhiS + (kt & 1) * KSTG;
        const uint32_t* Klo = KloS + (kt & 1) * KSTG;
        const float*    Vs  = VsS  + (kt & 1) * VSTG;
        const int k0 = kt * 64;

        // ---- Bias loads early (hidden behind QK MMAs) ----
        float2 bq0[8], bq1[8];
        #pragma unroll
        for (int ns = 0; ns < 8; ns++) {
            int col = k0 + ns * 8 + 2 * t;
            bq0[ns] = *(const float2*)&Bg[(size_t)(w * 16 + g) * SQ + col];
            bq1[ns] = *(const float2*)&Bg[(size_t)(w * 16 + g + 8) * SQ + col];
        }

        // ---- S = Q @ K^T (bf16x3, B-frags via ldmatrix.x4) ----
        float s[8][4] = {};
        #pragma unroll
        for (int kk = 0; kk < 4; kk++) {
            #pragma unroll
            for (int np = 0; np < 4; np++) {
                uint32_t a_hi = smaddr(Khi + ((2 * np + (lm_m >> 1)) * 8 + lm_r) * KP
                                           + kk * 8 + (lm_m & 1) * 4);
                uint32_t a_lo = smaddr(Klo + ((2 * np + (lm_m >> 1)) * 8 + lm_r) * KP
                                           + kk * 8 + (lm_m & 1) * 4);
                uint32_t bh0a, bh1a, bh0b, bh1b, bl0a, bl1a, bl0b, bl1b;
                ldsm_x4(bh0a, bh1a, bh0b, bh1b, a_hi);
                ldsm_x4(bl0a, bl1a, bl0b, bl1b, a_lo);
                mma_bf16(s[2*np],   qh[kk][0], qh[kk][1], qh[kk][2], qh[kk][3], bh0a, bh1a);
                mma_bf16(s[2*np],   qh[kk][0], qh[kk][1], qh[kk][2], qh[kk][3], bl0a, bl1a);
                mma_bf16(s[2*np],   ql[kk][0], ql[kk][1], ql[kk][2], ql[kk][3], bh0a, bh1a);
                mma_bf16(s[2*np+1], qh[kk][0], qh[kk][1], qh[kk][2], qh[kk][3], bh0b, bh1b);
                mma_bf16(s[2*np+1], qh[kk][0], qh[kk][1], qh[kk][2], qh[kk][3], bl0b, bl1b);
                mma_bf16(s[2*np+1], ql[kk][0], ql[kk][1], ql[kk][2], ql[kk][3], bh0b, bh1b);
            }
        }

        #pragma unroll
        for (int ns = 0; ns < 8; ns++) {
            s[ns][0] += bq0[ns].x; s[ns][1] += bq0[ns].y;
            s[ns][2] += bq1[ns].x; s[ns][3] += bq1[ns].y;
        }

        // ---- Online softmax (exp2, registers + quad shfl) ----
        float tm0 = -1e30f, tm1 = -1e30f;
        #pragma unroll
        for (int ns = 0; ns < 8; ns++) {
            tm0 = fmaxf(tm0, fmaxf(s[ns][0], s[ns][1]));
            tm1 = fmaxf(tm1, fmaxf(s[ns][2], s[ns][3]));
        }
        tm0 = fmaxf(tm0, __shfl_xor_sync(0xffffffffu, tm0, 1));
        tm0 = fmaxf(tm0, __shfl_xor_sync(0xffffffffu, tm0, 2));
        tm1 = fmaxf(tm1, __shfl_xor_sync(0xffffffffu, tm1, 1));
        tm1 = fmaxf(tm1, __shfl_xor_sync(0xffffffffu, tm1, 2));

        float mn0 = fmaxf(mrow[0], tm0), mn1 = fmaxf(mrow[1], tm1);
        float cr0 = exp2f(mrow[0] - mn0), cr1 = exp2f(mrow[1] - mn1);
        float sum0 = 0.0f, sum1 = 0.0f;
        const int prow = w * 16 + g;
        #pragma unroll
        for (int ns = 0; ns < 8; ns++) {
            float p0 = exp2f(s[ns][0] - mn0);
            float p1 = exp2f(s[ns][1] - mn0);
            float p2 = exp2f(s[ns][2] - mn1);
            float p3 = exp2f(s[ns][3] - mn1);
            sum0 += p0 + p1; sum1 += p2 + p3;
            int pc = ns * 8 + 2 * t;
            Ps[prow * PP + pc]           = p0;   // raw fp32; tf32 MMA truncates
            Ps[prow * PP + pc + 1]       = p1;
            Ps[(prow + 8) * PP + pc]     = p2;
            Ps[(prow + 8) * PP + pc + 1] = p3;
            o[ns][0] *= cr0; o[ns][1] *= cr0;
            o[ns][2] *= cr1; o[ns][3] *= cr1;
        }
        sum0 += __shfl_xor_sync(0xffffffffu, sum0, 1);
        sum0 += __shfl_xor_sync(0xffffffffu, sum0, 2);
        sum1 += __shfl_xor_sync(0xffffffffu, sum1, 1);
        sum1 += __shfl_xor_sync(0xffffffffu, sum1, 2);
        lrow[0] = lrow[0] * cr0 + sum0;
        lrow[1] = lrow[1] * cr1 + sum1;
        mrow[0] = mn0; mrow[1] = mn1;
        __syncwarp();

        // ---- O += P @ V (tf32 single-pass) ----
        #pragma unroll
        for (int kk = 0; kk < 8; kk++) {
            uint32_t a0 = __float_as_uint(Ps[prow * PP + kk * 8 + t]);
            uint32_t a1 = __float_as_uint(Ps[(prow + 8) * PP + kk * 8 + t]);
            uint32_t a2 = __float_as_uint(Ps[prow * PP + kk * 8 + t + 4]);
            uint32_t a3 = __float_as_uint(Ps[(prow + 8) * PP + kk * 8 + t + 4]);
            #pragma unroll
            for (int ns = 0; ns < 8; ns++) {
                uint32_t b0 = __float_as_uint(Vs[(kk * 8 + t) * VP + ns * 8 + g]);
                uint32_t b1 = __float_as_uint(Vs[(kk * 8 + t + 4) * VP + ns * 8 + g]);
                mma_tf32(o[ns], a0, a1, a2, a3, b0, b1);
            }
        }
    }

    // ---- Normalize + write ctx ----
    float inv0 = 1.0f / lrow[0], inv1 = 1.0f / lrow[1];
    float* Cg = g_ctx + ((size_t)b * SQ + q0) * DD + h * HD;
    #pragma unroll
    for (int ns = 0; ns < 8; ns++) {
        int col = ns * 8 + 2 * t;
        float2 v0 = make_float2(o[ns][0] * inv0, o[ns][1] * inv0);
        float2 v1 = make_float2(o[ns][2] * inv1, o[ns][3] * inv1);
        *(float2*)&Cg[(size_t)(w * 16 + g) * DD + col] = v0;
        *(float2*)&Cg[(size_t)(w * 16 + g + 8) * DD + col] = v1;
    }
}

// ---------------------------------------------------------------------------
extern "C" void kernel_launch(void* const* d_in, const int* in_sizes, int n_in,
                              void* d_out, int out_size)
{
    const float* x     = (const float*)d_in[0];
    const float* Wq    = (const float*)d_in[1];
    const float* bq    = (const float*)d_in[2];
    const float* Wk    = (const float*)d_in[3];
    const float* bk    = (const float*)d_in[4];
    const float* Wv    = (const float*)d_in[5];
    const float* bv    = (const float*)d_in[6];
    const float* Wo    = (const float*)d_in[7];
    const float* bo    = (const float*)d_in[8];
    const float* amask = (const float*)d_in[9];
    const float* ipa   = (const float*)d_in[10];
    const float* assoc = (const float*)d_in[11];
    const int* cid            = (const int*)d_in[12];       // int32 (JAX x64 off)
    const unsigned char* kpm  = (const unsigned char*)d_in[13];
    float* out = (float*)d_out;

    cudaFuncSetAttribute(attn_tc_kernel, cudaFuncAttributeMaxDynamicSharedMemorySize, ATTN_SMEM);

    // Fused QKV projections + combined bias (z = 3 plane)
    qkv_bias_kernel<<<dim3(DD / 64, (BB * SQ) / 128, 4), 256, GEMM_SMEM>>>(
        x, Wq, bq, Wk, bk, Wv, bv, ipa, assoc, amask, cid, kpm);

    // Tensor-core flash attention (2 CTAs/SM, cp.async pipelined)
    attn_tc_kernel<<<dim3(SQ / 128, NH, BB), 256, ATTN_SMEM>>>();

    // Output projection
    proj_tc_kernel<<<dim3(DD / 64, (BB * SQ) / 128), 256, GEMM_SMEM>>>(Wo, bo, out);
}